// round 6
// baseline (speedup 1.0000x reference)
#include <cuda_runtime.h>
#include <stdint.h>

#define NATOMS 10000
#define F      128
#define NEDGES 640000
#define KTOT   384   // [feat | S | deg*feat]
#define CAP    256   // per-node bucket capacity (deg ~ Poisson(64); P(>256) ~ 1e-80)

typedef unsigned long long u64;

// Scratch (static; no allocations allowed)
__device__ __align__(16) float g_S[NATOMS * F];   // sum of src features per dst node
__device__ int   g_deg[NATOMS];                   // in-degree per node (also fill cursor)
__device__ int   g_csr[NATOMS * CAP];             // src indices bucketed by dst (fixed cap)
__device__ int   g_is64;                          // 1 if edge dtype is int64
__device__ __align__(16) float g_W[KTOT * F];     // folded: [Wu_top; Wt@Wu_bot; Wb@Wu_bot]
__device__ float g_c[F];                          // b_msg @ Wu_bot

// ---------------------------------------------------------------------------
// Zero degrees + detect edge index dtype (int32 vs int64).
// ---------------------------------------------------------------------------
__global__ void zero_detect_kernel(const void* __restrict__ ei) {
    int i = blockIdx.x * blockDim.x + threadIdx.x;
    if (i < NATOMS) g_deg[i] = 0;
    if (i == 0) {
        const long long* p = (const long long*)ei;
        int is64 = 1;
        for (int k = 0; k < 8; ++k) {
            long long v = p[k];
            if (v < 0 || v >= NATOMS) { is64 = 0; break; }
        }
        g_is64 = is64;
    }
}

// ---------------------------------------------------------------------------
// Build buckets: pos = deg[dst]++ (atomic), csr[dst*CAP + pos] = src.
// 4 edges/thread for ILP (4 independent ATOMG chains in flight).
// ---------------------------------------------------------------------------
__global__ void __launch_bounds__(256) build_kernel(const void* __restrict__ ei) {
    int base = (blockIdx.x * blockDim.x + threadIdx.x) * 4;
    if (base >= NEDGES) return;                    // NEDGES % 4 == 0 -> full quads
    int s0, s1, s2, s3, d0, d1, d2, d3;
    if (g_is64) {
        const long long* ps = (const long long*)ei;
        const long long* pd = ps + NEDGES;
        s0 = (int)ps[base]; s1 = (int)ps[base + 1]; s2 = (int)ps[base + 2]; s3 = (int)ps[base + 3];
        d0 = (int)pd[base]; d1 = (int)pd[base + 1]; d2 = (int)pd[base + 2]; d3 = (int)pd[base + 3];
    } else {
        int4 sv = ((const int4*)((const int*)ei))[base >> 2];
        int4 dv = ((const int4*)((const int*)ei + NEDGES))[base >> 2];
        s0 = sv.x; s1 = sv.y; s2 = sv.z; s3 = sv.w;
        d0 = dv.x; d1 = dv.y; d2 = dv.z; d3 = dv.w;
    }
    int p0 = atomicAdd(&g_deg[d0], 1);
    int p1 = atomicAdd(&g_deg[d1], 1);
    int p2 = atomicAdd(&g_deg[d2], 1);
    int p3 = atomicAdd(&g_deg[d3], 1);
    g_csr[d0 * CAP + p0] = s0;
    g_csr[d1 * CAP + p1] = s1;
    g_csr[d2 * CAP + p2] = s2;
    g_csr[d3 * CAP + p3] = s3;
}

// ---------------------------------------------------------------------------
// Gather: one warp per dst node. Accumulate 128 floats (float4 per lane) over
// all incoming edges. feat rows (512B) read coalesced; feat is L2-resident.
// ---------------------------------------------------------------------------
__global__ void __launch_bounds__(256) gather_kernel(const float* __restrict__ feat) {
    int warp = (blockIdx.x * blockDim.x + threadIdx.x) >> 5;
    int lane = threadIdx.x & 31;
    if (warp >= NATOMS) return;

    const int* bucket = g_csr + warp * CAP;
    int n  = g_deg[warp];
    int j  = 0;
    float4 acc = make_float4(0.f, 0.f, 0.f, 0.f);

    while (n - j >= 32) {
        int s = bucket[j + lane];
#pragma unroll
        for (int i = 0; i < 32; i += 4) {
            int s0 = __shfl_sync(0xffffffffu, s, i);
            int s1 = __shfl_sync(0xffffffffu, s, i + 1);
            int s2 = __shfl_sync(0xffffffffu, s, i + 2);
            int s3 = __shfl_sync(0xffffffffu, s, i + 3);
            float4 v0 = __ldg((const float4*)feat + s0 * 32 + lane);
            float4 v1 = __ldg((const float4*)feat + s1 * 32 + lane);
            float4 v2 = __ldg((const float4*)feat + s2 * 32 + lane);
            float4 v3 = __ldg((const float4*)feat + s3 * 32 + lane);
            acc.x += v0.x; acc.y += v0.y; acc.z += v0.z; acc.w += v0.w;
            acc.x += v1.x; acc.y += v1.y; acc.z += v1.z; acc.w += v1.w;
            acc.x += v2.x; acc.y += v2.y; acc.z += v2.z; acc.w += v2.w;
            acc.x += v3.x; acc.y += v3.y; acc.z += v3.z; acc.w += v3.w;
        }
        j += 32;
    }
    if (j < n) {
        int rem = n - j;
        int s = (lane < rem) ? bucket[j + lane] : 0;
        for (int i = 0; i < rem; ++i) {
            int si = __shfl_sync(0xffffffffu, s, i);
            float4 v = __ldg((const float4*)feat + si * 32 + lane);
            acc.x += v.x; acc.y += v.y; acc.z += v.z; acc.w += v.w;
        }
    }
    ((float4*)g_S)[warp * 32 + lane] = acc;
}

// ---------------------------------------------------------------------------
// Fold weights: g_W rows 0..127 = Wu_top, 128..255 = Wt@Wu_bot, 256..383 = Wb@Wu_bot
// g_c = b_msg @ Wu_bot
// ---------------------------------------------------------------------------
__global__ void prep_kernel(const float* __restrict__ W_msg,
                            const float* __restrict__ b_msg,
                            const float* __restrict__ W_upd) {
    int j = threadIdx.x;     // output column 0..127
    int i = blockIdx.x;
    if (i < 128) {
        float a = 0.f, b = 0.f;
#pragma unroll 8
        for (int k = 0; k < 128; ++k) {
            float wu = W_upd[(128 + k) * F + j];        // Wu_bot[k][j]
            a += W_msg[i * F + k]         * wu;         // Wt row i
            b += W_msg[(128 + i) * F + k] * wu;         // Wb row i
        }
        g_W[(128 + i) * F + j] = a;
        g_W[(256 + i) * F + j] = b;
    } else {
        for (int r = 0; r < 128; ++r)
            g_W[r * F + j] = W_upd[r * F + j];
        float c = 0.f;
#pragma unroll 8
        for (int k = 0; k < 128; ++k)
            c += b_msg[k] * W_upd[(128 + k) * F + j];
        g_c[j] = c;
    }
}

// ---------------------------------------------------------------------------
// Packed fp32x2 FMA (FFMA2) — 2 fp32 FMAs per issue slot, PTX-only.
// ---------------------------------------------------------------------------
__device__ __forceinline__ void ffma2(u64& acc, u64 a, u64 b) {
    asm("fma.rn.f32x2 %0, %1, %2, %0;" : "+l"(acc) : "l"(a), "l"(b));
}
__device__ __forceinline__ u64 pack2(float a) {
    u64 r;
    asm("mov.b64 %0, {%1, %1};" : "=l"(r) : "f"(a));
    return r;
}

// ---------------------------------------------------------------------------
// Output GEMM: out[10000,128] = X @ g_W + deg*c + b_upd,
//   X = [feat | S | deg*feat]  (K=384), computed on the fly.
// Tile: 72 rows x 128 cols, 288 threads (18x16), thread tile 4x8, BK=32.
// 139 blocks <= 148 SMs -> one wave. Inner loop in f32x2 packed FMA.
// ---------------------------------------------------------------------------
__global__ void __launch_bounds__(288) out_gemm(const float* __restrict__ feat,
                                                const float* __restrict__ b_upd,
                                                float* __restrict__ out) {
    __shared__ __align__(16) float Xs[72][36];
    __shared__ __align__(16) float Ws[32][128];

    int tid = threadIdx.x;
    int tx  = tid & 15;              // col group (8 cols)
    int ty  = tid >> 4;              // row group (4 rows), 0..17
    int bm  = blockIdx.x * 72;

    u64 acc2[4][4];                  // 4 rows x 4 f32x2 pairs (8 cols)
#pragma unroll
    for (int i = 0; i < 4; ++i)
#pragma unroll
        for (int j = 0; j < 4; ++j) acc2[i][j] = 0ull;

#pragma unroll 1
    for (int t = 0; t < KTOT / 32; ++t) {
        int k0 = t * 32;
        // ---- X tile: 72 rows x 32 k = 576 float4; 2 per thread ----
#pragma unroll
        for (int i = 0; i < 2; ++i) {
            int idx = tid + i * 288;
            int r   = idx >> 3;              // 0..71
            int kq  = (idx & 7) << 2;        // 0,4,...,28
            int row = bm + r;
            int k   = k0 + kq;
            float4 v = make_float4(0.f, 0.f, 0.f, 0.f);
            float  s = 1.f;
            if (row < NATOMS) {
                if (k < 128) {
                    v = __ldg((const float4*)feat + row * 32 + (k >> 2));
                } else if (k < 256) {
                    v = *((const float4*)g_S + row * 32 + ((k - 128) >> 2));
                } else {
                    v = __ldg((const float4*)feat + row * 32 + ((k - 256) >> 2));
                    s = (float)g_deg[row];
                }
            }
            *(float4*)&Xs[r][kq] = make_float4(v.x * s, v.y * s, v.z * s, v.w * s);
        }
        // ---- W tile: 32 x 128 = 1024 float4; up to 4 per thread ----
#pragma unroll
        for (int i = 0; i < 4; ++i) {
            int idx = tid + i * 288;
            if (idx < 1024) {
                int kr = idx >> 5;              // 0..31
                int c4 = (idx & 31) << 2;       // 0..124
                *(float4*)&Ws[kr][c4] = *((const float4*)g_W + (k0 + kr) * 32 + (c4 >> 2));
            }
        }
        __syncthreads();

#pragma unroll
        for (int kk = 0; kk < 32; ++kk) {
            u64 a0 = pack2(Xs[ty * 4 + 0][kk]);
            u64 a1 = pack2(Xs[ty * 4 + 1][kk]);
            u64 a2 = pack2(Xs[ty * 4 + 2][kk]);
            u64 a3 = pack2(Xs[ty * 4 + 3][kk]);
            const u64* bp = (const u64*)&Ws[kk][tx * 8];   // 2x LDS.128 worth
            u64 b0 = bp[0], b1 = bp[1], b2 = bp[2], b3 = bp[3];
            ffma2(acc2[0][0], a0, b0); ffma2(acc2[0][1], a0, b1); ffma2(acc2[0][2], a0, b2); ffma2(acc2[0][3], a0, b3);
            ffma2(acc2[1][0], a1, b0); ffma2(acc2[1][1], a1, b1); ffma2(acc2[1][2], a1, b2); ffma2(acc2[1][3], a1, b3);
            ffma2(acc2[2][0], a2, b0); ffma2(acc2[2][1], a2, b1); ffma2(acc2[2][2], a2, b2); ffma2(acc2[2][3], a2, b3);
            ffma2(acc2[3][0], a3, b0); ffma2(acc2[3][1], a3, b1); ffma2(acc2[3][2], a3, b2); ffma2(acc2[3][3], a3, b3);
        }
        __syncthreads();
    }

    // ---- epilogue: + deg*c + b_upd ----
    int col = tx * 8;
    float cv[8], bv[8];
#pragma unroll
    for (int j = 0; j < 8; ++j) {
        cv[j] = g_c[col + j];
        bv[j] = __ldg(&b_upd[col + j]);
    }
#pragma unroll
    for (int i = 0; i < 4; ++i) {
        int row = bm + ty * 4 + i;
        if (row < NATOMS) {
            float d = (float)g_deg[row];
            float2 p[4];
#pragma unroll
            for (int j = 0; j < 4; ++j) {
                float2 v = *(float2*)&acc2[i][j];
                p[j].x = v.x + d * cv[j * 2 + 0] + bv[j * 2 + 0];
                p[j].y = v.y + d * cv[j * 2 + 1] + bv[j * 2 + 1];
            }
            float4 o0 = make_float4(p[0].x, p[0].y, p[1].x, p[1].y);
            float4 o1 = make_float4(p[2].x, p[2].y, p[3].x, p[3].y);
            *((float4*)out + row * 32 + (col >> 2))     = o0;
            *((float4*)out + row * 32 + (col >> 2) + 1) = o1;
        }
    }
}

// ---------------------------------------------------------------------------
extern "C" void kernel_launch(void* const* d_in, const int* in_sizes, int n_in,
                              void* d_out, int out_size) {
    const float* feat  = (const float*)d_in[0];
    const void*  ei    = d_in[1];
    const float* W_msg = (const float*)d_in[2];
    const float* b_msg = (const float*)d_in[3];
    const float* W_upd = (const float*)d_in[4];
    const float* b_upd = (const float*)d_in[5];
    float*       out   = (float*)d_out;

    zero_detect_kernel<<<(NATOMS + 255) / 256, 256>>>(ei);
    prep_kernel<<<129, 128>>>(W_msg, b_msg, W_upd);
    build_kernel<<<(NEDGES / 4 + 255) / 256, 256>>>(ei);
    gather_kernel<<<(NATOMS * 32 + 255) / 256, 256>>>(feat);
    out_gemm<<<(NATOMS + 71) / 72, 288>>>(feat, b_upd, out);
}

// round 7
// speedup vs baseline: 1.1342x; 1.1342x over previous
#include <cuda_runtime.h>
#include <cuda_fp16.h>
#include <stdint.h>

#define NATOMS 10000
#define F      128
#define NEDGES 640000
#define KTOT   384   // [feat | S | deg*feat]
#define CAP    256   // per-node bucket capacity (deg ~ Poisson(64); P(>256) ~ 1e-80)

typedef unsigned long long u64;

// Scratch (static; no allocations allowed)
__device__ __align__(16) float  g_S[NATOMS * F];      // sum of src features per dst node
__device__ __align__(16) __half g_f16[NATOMS * F];    // fp16 copy of feat (gather path only)
__device__ int   g_deg[NATOMS];                       // in-degree per node (also fill cursor)
__device__ int   g_csr[NATOMS * CAP];                 // src indices bucketed by dst
__device__ int   g_is64;                              // 1 if edge dtype is int64
__device__ __align__(16) float g_W[KTOT * F];         // folded: [Wu_top; Wt@Wu_bot; Wb@Wu_bot]
__device__ float g_c[F];                              // b_msg @ Wu_bot

// ---------------------------------------------------------------------------
// Fused pre-pass: fp16 convert + deg zero + dtype detect + weight fold.
// Grid: 1250 blocks x 256 threads (= 320000 = NATOMS*F/4 float4s).
// Blocks 0..127 additionally fold one row-pair of Wt@Wu_bot / Wb@Wu_bot;
// block 128 copies Wu_top and computes g_c.
// ---------------------------------------------------------------------------
__global__ void __launch_bounds__(256) pre_kernel(const float* __restrict__ feat,
                                                  const void*  __restrict__ ei,
                                                  const float* __restrict__ W_msg,
                                                  const float* __restrict__ b_msg,
                                                  const float* __restrict__ W_upd) {
    int b = blockIdx.x, t = threadIdx.x;
    int gi = b * 256 + t;

    // fp32 -> fp16 conversion (one float4 -> one uint2 of 4 halves)
    {
        float4 v = __ldg((const float4*)feat + gi);
        __half2 h0 = __float22half2_rn(make_float2(v.x, v.y));
        __half2 h1 = __float22half2_rn(make_float2(v.z, v.w));
        uint2 p;
        p.x = *(unsigned*)&h0;
        p.y = *(unsigned*)&h1;
        ((uint2*)g_f16)[gi] = p;
    }
    if (gi < NATOMS) g_deg[gi] = 0;
    if (gi == 0) {
        const long long* p = (const long long*)ei;
        int is64 = 1;
        for (int k = 0; k < 8; ++k) {
            long long v = p[k];
            if (v < 0 || v >= NATOMS) { is64 = 0; break; }
        }
        g_is64 = is64;
    }

    // weight fold
    int j = t & 127, half = t >> 7;
    if (b < 128) {
        int i = b;
        float acc = 0.f;
        if (half == 0) {
#pragma unroll 8
            for (int k = 0; k < 128; ++k)
                acc += W_msg[i * F + k] * W_upd[(128 + k) * F + j];       // Wt row i
            g_W[(128 + i) * F + j] = acc;
        } else {
#pragma unroll 8
            for (int k = 0; k < 128; ++k)
                acc += W_msg[(128 + i) * F + k] * W_upd[(128 + k) * F + j]; // Wb row i
            g_W[(256 + i) * F + j] = acc;
        }
    } else if (b == 128) {
        for (int r = half * 64; r < half * 64 + 64; ++r)
            g_W[r * F + j] = W_upd[r * F + j];
        if (half == 0) {
            float c = 0.f;
#pragma unroll 8
            for (int k = 0; k < 128; ++k)
                c += b_msg[k] * W_upd[(128 + k) * F + j];
            g_c[j] = c;
        }
    }
}

// ---------------------------------------------------------------------------
// Build buckets: pos = deg[dst]++ (atomic), csr[dst*CAP + pos] = src.
// 4 edges/thread for ILP.
// ---------------------------------------------------------------------------
__global__ void __launch_bounds__(256) build_kernel(const void* __restrict__ ei) {
    int base = (blockIdx.x * blockDim.x + threadIdx.x) * 4;
    if (base >= NEDGES) return;                    // NEDGES % 4 == 0 -> full quads
    int s0, s1, s2, s3, d0, d1, d2, d3;
    if (g_is64) {
        const long long* ps = (const long long*)ei;
        const long long* pd = ps + NEDGES;
        s0 = (int)ps[base]; s1 = (int)ps[base + 1]; s2 = (int)ps[base + 2]; s3 = (int)ps[base + 3];
        d0 = (int)pd[base]; d1 = (int)pd[base + 1]; d2 = (int)pd[base + 2]; d3 = (int)pd[base + 3];
    } else {
        int4 sv = ((const int4*)((const int*)ei))[base >> 2];
        int4 dv = ((const int4*)((const int*)ei + NEDGES))[base >> 2];
        s0 = sv.x; s1 = sv.y; s2 = sv.z; s3 = sv.w;
        d0 = dv.x; d1 = dv.y; d2 = dv.z; d3 = dv.w;
    }
    int p0 = atomicAdd(&g_deg[d0], 1);
    int p1 = atomicAdd(&g_deg[d1], 1);
    int p2 = atomicAdd(&g_deg[d2], 1);
    int p3 = atomicAdd(&g_deg[d3], 1);
    g_csr[d0 * CAP + p0] = s0;
    g_csr[d1 * CAP + p1] = s1;
    g_csr[d2 * CAP + p2] = s2;
    g_csr[d3 * CAP + p3] = s3;
}

// ---------------------------------------------------------------------------
// Gather (fp16 rows): one warp per dst node. Each lane owns 4 features
// (one uint2 = 4 halves per row), accumulates in fp32. 256B/row from L2.
// 8 loads in flight per warp.
// ---------------------------------------------------------------------------
__device__ __forceinline__ void acc_h4(float4& acc, uint2 p) {
    __half2 h0 = *(__half2*)&p.x;
    __half2 h1 = *(__half2*)&p.y;
    float2 f0 = __half22float2(h0);
    float2 f1 = __half22float2(h1);
    acc.x += f0.x; acc.y += f0.y; acc.z += f1.x; acc.w += f1.y;
}

__global__ void __launch_bounds__(256) gather_kernel() {
    int warp = (blockIdx.x * blockDim.x + threadIdx.x) >> 5;
    int lane = threadIdx.x & 31;
    if (warp >= NATOMS) return;

    const int* bucket = g_csr + warp * CAP;
    const uint2* f16 = (const uint2*)g_f16;        // 32 uint2 per row
    int n = g_deg[warp];
    int j = 0;
    float4 acc = make_float4(0.f, 0.f, 0.f, 0.f);

    while (n - j >= 32) {
        int s = bucket[j + lane];
#pragma unroll
        for (int i = 0; i < 32; i += 8) {
            uint2 v[8];
#pragma unroll
            for (int q = 0; q < 8; ++q) {
                int sq = __shfl_sync(0xffffffffu, s, i + q);
                v[q] = __ldg(f16 + sq * 32 + lane);
            }
#pragma unroll
            for (int q = 0; q < 8; ++q) acc_h4(acc, v[q]);
        }
        j += 32;
    }
    if (j < n) {
        int rem = n - j;
        int s = (lane < rem) ? bucket[j + lane] : 0;
        for (int i = 0; i < rem; ++i) {
            int si = __shfl_sync(0xffffffffu, s, i);
            uint2 v = __ldg(f16 + si * 32 + lane);
            acc_h4(acc, v);
        }
    }
    ((float4*)g_S)[warp * 32 + lane] = acc;
}

// ---------------------------------------------------------------------------
// Packed fp32x2 FMA (FFMA2).
// ---------------------------------------------------------------------------
__device__ __forceinline__ void ffma2(u64& acc, u64 a, u64 b) {
    asm("fma.rn.f32x2 %0, %1, %2, %0;" : "+l"(acc) : "l"(a), "l"(b));
}
__device__ __forceinline__ u64 pack2(float a) {
    u64 r;
    asm("mov.b64 %0, {%1, %1};" : "=l"(r) : "f"(a));
    return r;
}

// ---------------------------------------------------------------------------
// Output GEMM: out[10000,128] = X @ g_W + deg*c + b_upd,
//   X = [feat | S | deg*feat]  (K=384), computed on the fly (fp32 exact).
// Tile: 72 rows x 128 cols, 288 threads, thread tile 4x8, BK=32, one wave.
// ---------------------------------------------------------------------------
__global__ void __launch_bounds__(288) out_gemm(const float* __restrict__ feat,
                                                const float* __restrict__ b_upd,
                                                float* __restrict__ out) {
    __shared__ __align__(16) float Xs[72][36];
    __shared__ __align__(16) float Ws[32][128];

    int tid = threadIdx.x;
    int tx  = tid & 15;              // col group (8 cols)
    int ty  = tid >> 4;              // row group (4 rows), 0..17
    int bm  = blockIdx.x * 72;

    u64 acc2[4][4];
#pragma unroll
    for (int i = 0; i < 4; ++i)
#pragma unroll
        for (int j = 0; j < 4; ++j) acc2[i][j] = 0ull;

#pragma unroll 1
    for (int t = 0; t < KTOT / 32; ++t) {
        int k0 = t * 32;
#pragma unroll
        for (int i = 0; i < 2; ++i) {
            int idx = tid + i * 288;
            int r   = idx >> 3;
            int kq  = (idx & 7) << 2;
            int row = bm + r;
            int k   = k0 + kq;
            float4 v = make_float4(0.f, 0.f, 0.f, 0.f);
            float  s = 1.f;
            if (row < NATOMS) {
                if (k < 128) {
                    v = __ldg((const float4*)feat + row * 32 + (k >> 2));
                } else if (k < 256) {
                    v = *((const float4*)g_S + row * 32 + ((k - 128) >> 2));
                } else {
                    v = __ldg((const float4*)feat + row * 32 + ((k - 256) >> 2));
                    s = (float)g_deg[row];
                }
            }
            *(float4*)&Xs[r][kq] = make_float4(v.x * s, v.y * s, v.z * s, v.w * s);
        }
#pragma unroll
        for (int i = 0; i < 4; ++i) {
            int idx = tid + i * 288;
            if (idx < 1024) {
                int kr = idx >> 5;
                int c4 = (idx & 31) << 2;
                *(float4*)&Ws[kr][c4] = *((const float4*)g_W + (k0 + kr) * 32 + (c4 >> 2));
            }
        }
        __syncthreads();

#pragma unroll
        for (int kk = 0; kk < 32; ++kk) {
            u64 a0 = pack2(Xs[ty * 4 + 0][kk]);
            u64 a1 = pack2(Xs[ty * 4 + 1][kk]);
            u64 a2 = pack2(Xs[ty * 4 + 2][kk]);
            u64 a3 = pack2(Xs[ty * 4 + 3][kk]);
            const u64* bp = (const u64*)&Ws[kk][tx * 8];
            u64 b0 = bp[0], b1 = bp[1], b2 = bp[2], b3 = bp[3];
            ffma2(acc2[0][0], a0, b0); ffma2(acc2[0][1], a0, b1); ffma2(acc2[0][2], a0, b2); ffma2(acc2[0][3], a0, b3);
            ffma2(acc2[1][0], a1, b0); ffma2(acc2[1][1], a1, b1); ffma2(acc2[1][2], a1, b2); ffma2(acc2[1][3], a1, b3);
            ffma2(acc2[2][0], a2, b0); ffma2(acc2[2][1], a2, b1); ffma2(acc2[2][2], a2, b2); ffma2(acc2[2][3], a2, b3);
            ffma2(acc2[3][0], a3, b0); ffma2(acc2[3][1], a3, b1); ffma2(acc2[3][2], a3, b2); ffma2(acc2[3][3], a3, b3);
        }
        __syncthreads();
    }

    int col = tx * 8;
    float cv[8], bv[8];
#pragma unroll
    for (int j = 0; j < 8; ++j) {
        cv[j] = g_c[col + j];
        bv[j] = __ldg(&b_upd[col + j]);
    }
#pragma unroll
    for (int i = 0; i < 4; ++i) {
        int row = bm + ty * 4 + i;
        if (row < NATOMS) {
            float d = (float)g_deg[row];
            float2 p[4];
#pragma unroll
            for (int j = 0; j < 4; ++j) {
                float2 v = *(float2*)&acc2[i][j];
                p[j].x = v.x + d * cv[j * 2 + 0] + bv[j * 2 + 0];
                p[j].y = v.y + d * cv[j * 2 + 1] + bv[j * 2 + 1];
            }
            *((float4*)out + row * 32 + (col >> 2))     = make_float4(p[0].x, p[0].y, p[1].x, p[1].y);
            *((float4*)out + row * 32 + (col >> 2) + 1) = make_float4(p[2].x, p[2].y, p[3].x, p[3].y);
        }
    }
}

// ---------------------------------------------------------------------------
extern "C" void kernel_launch(void* const* d_in, const int* in_sizes, int n_in,
                              void* d_out, int out_size) {
    const float* feat  = (const float*)d_in[0];
    const void*  ei    = d_in[1];
    const float* W_msg = (const float*)d_in[2];
    const float* b_msg = (const float*)d_in[3];
    const float* W_upd = (const float*)d_in[4];
    const float* b_upd = (const float*)d_in[5];
    float*       out   = (float*)d_out;

    pre_kernel<<<1250, 256>>>(feat, ei, W_msg, b_msg, W_upd);
    build_kernel<<<(NEDGES / 4 + 255) / 256, 256>>>(ei);
    gather_kernel<<<(NATOMS * 32 + 255) / 256, 256>>>();
    out_gemm<<<(NATOMS + 71) / 72, 288>>>(feat, b_upd, out);
}

// round 8
// speedup vs baseline: 1.1700x; 1.0316x over previous
#include <cuda_runtime.h>
#include <cuda_fp16.h>
#include <stdint.h>

#define NATOMS 10000
#define F      128
#define NEDGES 640000
#define CAP    256   // per-node bucket capacity (deg ~ Poisson(64); P(>256) ~ 1e-80)

typedef unsigned long long u64;

// Scratch (static; no allocations allowed)
__device__ __align__(16) float  g_S[NATOMS * F];      // sum of src features per dst node
__device__ __align__(16) __half g_f16[NATOMS * F];    // fp16 copy of feat (gather path only)
__device__ __align__(16) int    g_deg[NATOMS];        // in-degree per node (also fill cursor)
__device__ int   g_csr[NATOMS * CAP];                 // src indices bucketed by dst
__device__ int   g_is64;                              // 1 if edge dtype is int64
__device__ __align__(16) float g_W[384 * F];          // folded: [Wu_top; Wt@Wu_bot; Wb@Wu_bot]
__device__ float g_c[F];                              // b_msg @ Wu_bot

// ---------------------------------------------------------------------------
// Fused pre-pass: fp16 convert + deg zero + dtype detect + weight fold.
// ---------------------------------------------------------------------------
__global__ void __launch_bounds__(256) pre_kernel(const float* __restrict__ feat,
                                                  const void*  __restrict__ ei,
                                                  const float* __restrict__ W_msg,
                                                  const float* __restrict__ b_msg,
                                                  const float* __restrict__ W_upd) {
    int b = blockIdx.x, t = threadIdx.x;
    int gi = b * 256 + t;

    {   // fp32 -> fp16 conversion (one float4 -> 4 halves)
        float4 v = __ldg((const float4*)feat + gi);
        __half2 h0 = __float22half2_rn(make_float2(v.x, v.y));
        __half2 h1 = __float22half2_rn(make_float2(v.z, v.w));
        uint2 p;
        p.x = *(unsigned*)&h0;
        p.y = *(unsigned*)&h1;
        ((uint2*)g_f16)[gi] = p;
    }
    if (gi < NATOMS) g_deg[gi] = 0;
    if (gi == 0) {
        const long long* p = (const long long*)ei;
        int is64 = 1;
        for (int k = 0; k < 8; ++k) {
            long long v = p[k];
            if (v < 0 || v >= NATOMS) { is64 = 0; break; }
        }
        g_is64 = is64;
    }

    int j = t & 127, half = t >> 7;
    if (b < 128) {
        int i = b;
        float acc = 0.f;
        if (half == 0) {
#pragma unroll 8
            for (int k = 0; k < 128; ++k)
                acc += W_msg[i * F + k] * W_upd[(128 + k) * F + j];         // Wt row i
            g_W[(128 + i) * F + j] = acc;
        } else {
#pragma unroll 8
            for (int k = 0; k < 128; ++k)
                acc += W_msg[(128 + i) * F + k] * W_upd[(128 + k) * F + j]; // Wb row i
            g_W[(256 + i) * F + j] = acc;
        }
    } else if (b == 128) {
        for (int r = half * 64; r < half * 64 + 64; ++r)
            g_W[r * F + j] = W_upd[r * F + j];
        if (half == 0) {
            float c = 0.f;
#pragma unroll 8
            for (int k = 0; k < 128; ++k)
                c += b_msg[k] * W_upd[(128 + k) * F + j];
            g_c[j] = c;
        }
    }
}

// ---------------------------------------------------------------------------
// Build buckets: pos = deg[dst]++ (atomic), csr[dst*CAP + pos] = src.
// ---------------------------------------------------------------------------
__global__ void __launch_bounds__(256) build_kernel(const void* __restrict__ ei) {
    int base = (blockIdx.x * blockDim.x + threadIdx.x) * 4;
    if (base >= NEDGES) return;
    int s0, s1, s2, s3, d0, d1, d2, d3;
    if (g_is64) {
        const long long* ps = (const long long*)ei;
        const long long* pd = ps + NEDGES;
        s0 = (int)ps[base]; s1 = (int)ps[base + 1]; s2 = (int)ps[base + 2]; s3 = (int)ps[base + 3];
        d0 = (int)pd[base]; d1 = (int)pd[base + 1]; d2 = (int)pd[base + 2]; d3 = (int)pd[base + 3];
    } else {
        int4 sv = ((const int4*)((const int*)ei))[base >> 2];
        int4 dv = ((const int4*)((const int*)ei + NEDGES))[base >> 2];
        s0 = sv.x; s1 = sv.y; s2 = sv.z; s3 = sv.w;
        d0 = dv.x; d1 = dv.y; d2 = dv.z; d3 = dv.w;
    }
    int p0 = atomicAdd(&g_deg[d0], 1);
    int p1 = atomicAdd(&g_deg[d1], 1);
    int p2 = atomicAdd(&g_deg[d2], 1);
    int p3 = atomicAdd(&g_deg[d3], 1);
    g_csr[d0 * CAP + p0] = s0;
    g_csr[d1 * CAP + p1] = s1;
    g_csr[d2 * CAP + p2] = s2;
    g_csr[d3 * CAP + p3] = s3;
}

// ---------------------------------------------------------------------------
// Gather (fp16 rows): one warp per dst node, fp32 accumulation.
// ---------------------------------------------------------------------------
__device__ __forceinline__ void acc_h4(float4& acc, uint2 p) {
    __half2 h0 = *(__half2*)&p.x;
    __half2 h1 = *(__half2*)&p.y;
    float2 f0 = __half22float2(h0);
    float2 f1 = __half22float2(h1);
    acc.x += f0.x; acc.y += f0.y; acc.z += f1.x; acc.w += f1.y;
}

__global__ void __launch_bounds__(256) gather_kernel() {
    int warp = (blockIdx.x * blockDim.x + threadIdx.x) >> 5;
    int lane = threadIdx.x & 31;
    if (warp >= NATOMS) return;

    const int* bucket = g_csr + warp * CAP;
    const uint2* f16 = (const uint2*)g_f16;        // 32 uint2 per row
    int n = g_deg[warp];
    int j = 0;
    float4 acc = make_float4(0.f, 0.f, 0.f, 0.f);

    while (n - j >= 32) {
        int s = bucket[j + lane];
#pragma unroll
        for (int i = 0; i < 32; i += 8) {
            uint2 v[8];
#pragma unroll
            for (int q = 0; q < 8; ++q) {
                int sq = __shfl_sync(0xffffffffu, s, i + q);
                v[q] = __ldg(f16 + sq * 32 + lane);
            }
#pragma unroll
            for (int q = 0; q < 8; ++q) acc_h4(acc, v[q]);
        }
        j += 32;
    }
    if (j < n) {
        int rem = n - j;
        int s = (lane < rem) ? bucket[j + lane] : 0;
        for (int i = 0; i < rem; ++i) {
            int si = __shfl_sync(0xffffffffu, s, i);
            uint2 v = __ldg(f16 + si * 32 + lane);
            acc_h4(acc, v);
        }
    }
    ((float4*)g_S)[warp * 32 + lane] = acc;
}

// ---------------------------------------------------------------------------
// Packed fp32x2 FMA (FFMA2).
// ---------------------------------------------------------------------------
__device__ __forceinline__ void ffma2(u64& acc, u64 a, u64 b) {
    asm("fma.rn.f32x2 %0, %1, %2, %0;" : "+l"(acc) : "l"(a), "l"(b));
}
__device__ __forceinline__ u64 pack2(float a) {
    u64 r;
    asm("mov.b64 %0, {%1, %1};" : "=l"(r) : "f"(a));
    return r;
}

// ---------------------------------------------------------------------------
// Output GEMM: out = feat@W0 + S@W1 + deg*(feat@W2) + deg*c + b_upd.
// 80 rows x 128 cols per block, 320 threads, grid=125 (exactly one wave,
// 125*80 == 10000, no bounds checks). Xs stored k-major (transposed) with
// pitch 84 -> conflict-free STS.128 writes and 1-wavefront a-loads.
// Feat tiles (t=0..3) feed TWO accumulator sets (W0 and W2) so feat is read
// once; deg applied in the epilogue. S tiles are t=4..7.
// Register-staged prefetch of tile t+1 overlaps GMEM with the inner loop.
// ---------------------------------------------------------------------------
#define GP 84   // Xs pitch (floats): mult of 4 (LDS.128 align), conflict-free STS

__global__ void __launch_bounds__(320) out_gemm(const float* __restrict__ feat,
                                                const float* __restrict__ b_upd,
                                                float* __restrict__ out) {
    __shared__ __align__(16) float  Xs[32][GP];     // [k][row]
    __shared__ __align__(16) float4 WsA[32][32];    // [k][col4] rows 0..255 of g_W
    __shared__ __align__(16) float4 WsB[32][32];    // [k][col4] rows 256..383 (t<4)

    int tid = threadIdx.x;
    int tx  = tid & 15;              // col group (8 cols)
    int ty  = tid >> 4;              // row group (4 rows), 0..19
    int bm  = blockIdx.x * 80;

    u64 accA[4][4], accQ[4][4];
#pragma unroll
    for (int i = 0; i < 4; ++i)
#pragma unroll
        for (int j = 0; j < 4; ++j) { accA[i][j] = 0ull; accQ[i][j] = 0ull; }

    // staging registers
    float  xv[2][4];
    float4 wv[7];

    // ---- load tile t into staging regs ----
    auto loadX = [&](int t) {
        const float* src = (t < 4) ? feat : g_S;
        int c0 = (t < 4) ? t * 32 : (t - 4) * 32;
#pragma unroll
        for (int i = 0; i < 2; ++i) {
            int idx = tid + i * 320;
            int k = idx & 31, r4 = idx >> 5;         // r4: 0..19
            const float* p = src + (bm + r4 * 4) * F + c0 + k;
#pragma unroll
            for (int jj = 0; jj < 4; ++jj) xv[i][jj] = __ldg(p + jj * F);
        }
    };
    auto loadW = [&](int t) {
        int n = (t < 4) ? 2048 : 1024;
#pragma unroll
        for (int i = 0; i < 7; ++i) {
            int idx = tid + i * 320;
            if (idx < n) {
                int half = idx >> 10;                // 0 = A (rows t*32), 1 = B (rows 256+t*32)
                int r    = (idx >> 5) & 31;
                int c4   = idx & 31;
                int grow = (half ? 256 : 0) + t * 32 + r;
                wv[i] = __ldg((const float4*)g_W + grow * 32 + c4);
            }
        }
    };
    auto storeXW = [&](int t) {
#pragma unroll
        for (int i = 0; i < 2; ++i) {
            int idx = tid + i * 320;
            int k = idx & 31, r4 = idx >> 5;
            *(float4*)&Xs[k][r4 * 4] = make_float4(xv[i][0], xv[i][1], xv[i][2], xv[i][3]);
        }
        int n = (t < 4) ? 2048 : 1024;
#pragma unroll
        for (int i = 0; i < 7; ++i) {
            int idx = tid + i * 320;
            if (idx < n) {
                int half = idx >> 10;
                int r    = (idx >> 5) & 31;
                int c4   = idx & 31;
                if (half) WsB[r][c4] = wv[i]; else WsA[r][c4] = wv[i];
            }
        }
    };

    loadX(0); loadW(0);
#pragma unroll 1
    for (int t = 0; t < 8; ++t) {
        storeXW(t);
        __syncthreads();
        if (t < 7) { loadX(t + 1); loadW(t + 1); }   // prefetch next tile (hidden by inner loop)
        if (t < 4) {
#pragma unroll
            for (int kk = 0; kk < 32; ++kk) {
                float4 av = *(float4*)&Xs[kk][ty * 4];
                u64 a0 = pack2(av.x), a1 = pack2(av.y), a2 = pack2(av.z), a3 = pack2(av.w);
                float4 bA0 = WsA[kk][tx * 2], bA1 = WsA[kk][tx * 2 + 1];
                float4 bB0 = WsB[kk][tx * 2], bB1 = WsB[kk][tx * 2 + 1];
                u64 b0 = ((u64*)&bA0)[0], b1 = ((u64*)&bA0)[1];
                u64 b2 = ((u64*)&bA1)[0], b3 = ((u64*)&bA1)[1];
                u64 q0 = ((u64*)&bB0)[0], q1 = ((u64*)&bB0)[1];
                u64 q2 = ((u64*)&bB1)[0], q3 = ((u64*)&bB1)[1];
                ffma2(accA[0][0], a0, b0); ffma2(accA[0][1], a0, b1); ffma2(accA[0][2], a0, b2); ffma2(accA[0][3], a0, b3);
                ffma2(accA[1][0], a1, b0); ffma2(accA[1][1], a1, b1); ffma2(accA[1][2], a1, b2); ffma2(accA[1][3], a1, b3);
                ffma2(accA[2][0], a2, b0); ffma2(accA[2][1], a2, b1); ffma2(accA[2][2], a2, b2); ffma2(accA[2][3], a2, b3);
                ffma2(accA[3][0], a3, b0); ffma2(accA[3][1], a3, b1); ffma2(accA[3][2], a3, b2); ffma2(accA[3][3], a3, b3);
                ffma2(accQ[0][0], a0, q0); ffma2(accQ[0][1], a0, q1); ffma2(accQ[0][2], a0, q2); ffma2(accQ[0][3], a0, q3);
                ffma2(accQ[1][0], a1, q0); ffma2(accQ[1][1], a1, q1); ffma2(accQ[1][2], a1, q2); ffma2(accQ[1][3], a1, q3);
                ffma2(accQ[2][0], a2, q0); ffma2(accQ[2][1], a2, q1); ffma2(accQ[2][2], a2, q2); ffma2(accQ[2][3], a2, q3);
                ffma2(accQ[3][0], a3, q0); ffma2(accQ[3][1], a3, q1); ffma2(accQ[3][2], a3, q2); ffma2(accQ[3][3], a3, q3);
            }
        } else {
#pragma unroll
            for (int kk = 0; kk < 32; ++kk) {
                float4 av = *(float4*)&Xs[kk][ty * 4];
                u64 a0 = pack2(av.x), a1 = pack2(av.y), a2 = pack2(av.z), a3 = pack2(av.w);
                float4 bA0 = WsA[kk][tx * 2], bA1 = WsA[kk][tx * 2 + 1];
                u64 b0 = ((u64*)&bA0)[0], b1 = ((u64*)&bA0)[1];
                u64 b2 = ((u64*)&bA1)[0], b3 = ((u64*)&bA1)[1];
                ffma2(accA[0][0], a0, b0); ffma2(accA[0][1], a0, b1); ffma2(accA[0][2], a0, b2); ffma2(accA[0][3], a0, b3);
                ffma2(accA[1][0], a1, b0); ffma2(accA[1][1], a1, b1); ffma2(accA[1][2], a1, b2); ffma2(accA[1][3], a1, b3);
                ffma2(accA[2][0], a2, b0); ffma2(accA[2][1], a2, b1); ffma2(accA[2][2], a2, b2); ffma2(accA[2][3], a2, b3);
                ffma2(accA[3][0], a3, b0); ffma2(accA[3][1], a3, b1); ffma2(accA[3][2], a3, b2); ffma2(accA[3][3], a3, b3);
            }
        }
        __syncthreads();
    }

    // ---- epilogue: out = accA + deg*(accQ + c) + b_upd ----
    int4 dvi = *(const int4*)&g_deg[bm + ty * 4];
    float dgs[4] = {(float)dvi.x, (float)dvi.y, (float)dvi.z, (float)dvi.w};
    int col = tx * 8;
    float cv[8], bv[8];
#pragma unroll
    for (int j = 0; j < 8; ++j) {
        cv[j] = g_c[col + j];
        bv[j] = __ldg(&b_upd[col + j]);
    }
#pragma unroll
    for (int i = 0; i < 4; ++i) {
        int row = bm + ty * 4 + i;
        float d = dgs[i];
        float o[8];
#pragma unroll
        for (int j = 0; j < 4; ++j) {
            float2 a = *(float2*)&accA[i][j];
            float2 q = *(float2*)&accQ[i][j];
            o[j * 2 + 0] = a.x + d * q.x + d * cv[j * 2 + 0] + bv[j * 2 + 0];
            o[j * 2 + 1] = a.y + d * q.y + d * cv[j * 2 + 1] + bv[j * 2 + 1];
        }
        *((float4*)out + row * 32 + (col >> 2))     = make_float4(o[0], o[1], o[2], o[3]);
        *((float4*)out + row * 32 + (col >> 2) + 1) = make_float4(o[4], o[5], o[6], o[7]);
    }
}

// ---------------------------------------------------------------------------
extern "C" void kernel_launch(void* const* d_in, const int* in_sizes, int n_in,
                              void* d_out, int out_size) {
    const float* feat  = (const float*)d_in[0];
    const void*  ei    = d_in[1];
    const float* W_msg = (const float*)d_in[2];
    const float* b_msg = (const float*)d_in[3];
    const float* W_upd = (const float*)d_in[4];
    const float* b_upd = (const float*)d_in[5];
    float*       out   = (float*)d_out;

    pre_kernel<<<1250, 256>>>(feat, ei, W_msg, b_msg, W_upd);
    build_kernel<<<(NEDGES / 4 + 255) / 256, 256>>>(ei);
    gather_kernel<<<(NATOMS * 32 + 255) / 256, 256>>>();
    out_gemm<<<125, 320>>>(feat, b_upd, out);
}

// round 9
// speedup vs baseline: 1.8169x; 1.5529x over previous
#include <cuda_runtime.h>
#include <cuda_fp16.h>
#include <stdint.h>

#define NATOMS 10000
#define NPAD   10112   // NATOMS rounded up to 128 (GEMM tile), tail zeroed
#define F      128
#define NEDGES 640000
#define CAP    256     // per-node bucket capacity (deg ~ Poisson(64); P(>256) ~ 1e-80)

typedef unsigned long long u64_t;

// Scratch (static; no allocations allowed)
__device__ __align__(16) __half g_X16[NPAD * 384];   // [feat | S | deg*feat] fp16
__device__ __align__(16) __half g_W16[384 * F];      // folded weights fp16 [k][n]
__device__ __align__(16) int    g_deg[NATOMS];       // in-degree (also fill cursor)
__device__ int   g_csr[NATOMS * CAP];                // src indices bucketed by dst
__device__ int   g_is64;                             // 1 if edge dtype is int64
__device__ float g_c[F];                             // b_msg @ Wu_bot (fp32)

// ---------------------------------------------------------------------------
// Fused pre-pass: feat->fp16 into X16 cols 0..127, zero tail rows, zero deg,
// dtype detect, weight fold (fp32 math -> fp16 store).
// Grid: 1250 x 256  (1250*256 = 320000 = NATOMS*F/4 float4s)
// ---------------------------------------------------------------------------
__global__ void __launch_bounds__(256) pre_kernel(const float* __restrict__ feat,
                                                  const void*  __restrict__ ei,
                                                  const float* __restrict__ W_msg,
                                                  const float* __restrict__ b_msg,
                                                  const float* __restrict__ W_upd) {
    int b = blockIdx.x, t = threadIdx.x;
    int gi = b * 256 + t;

    {   // fp32 -> fp16: float4 -> 4 halves, row-major into X16 (row stride 384)
        int row = gi >> 5, seg = gi & 31;
        float4 v = __ldg((const float4*)feat + gi);
        __half2 h0 = __float22half2_rn(make_float2(v.x, v.y));
        __half2 h1 = __float22half2_rn(make_float2(v.z, v.w));
        uint2 p;
        p.x = *(unsigned*)&h0;
        p.y = *(unsigned*)&h1;
        ((uint2*)g_X16)[row * 96 + seg] = p;         // 384 halves = 96 uint2 per row
    }
    // zero tail rows (rows 10000..10111, all 384 cols): 112*96 = 10752 uint2
    if (gi < 10752) ((uint2*)g_X16)[NATOMS * 96 + gi] = make_uint2(0u, 0u);
    if (gi < NATOMS) g_deg[gi] = 0;
    if (gi == 0) {
        const long long* p = (const long long*)ei;
        int is64 = 1;
        for (int k = 0; k < 8; ++k) {
            long long v = p[k];
            if (v < 0 || v >= NATOMS) { is64 = 0; break; }
        }
        g_is64 = is64;
    }

    int j = t & 127, half = t >> 7;
    if (b < 128) {
        int i = b;
        float acc = 0.f;
        if (half == 0) {
#pragma unroll 8
            for (int k = 0; k < 128; ++k)
                acc += W_msg[i * F + k] * W_upd[(128 + k) * F + j];          // Wt row i
            g_W16[(128 + i) * F + j] = __float2half(acc);
        } else {
#pragma unroll 8
            for (int k = 0; k < 128; ++k)
                acc += W_msg[(128 + i) * F + k] * W_upd[(128 + k) * F + j]; // Wb row i
            g_W16[(256 + i) * F + j] = __float2half(acc);
        }
    } else if (b == 128) {
        for (int r = half * 64; r < half * 64 + 64; ++r)
            g_W16[r * F + j] = __float2half(W_upd[r * F + j]);
        if (half == 0) {
            float c = 0.f;
#pragma unroll 8
            for (int k = 0; k < 128; ++k)
                c += b_msg[k] * W_upd[(128 + k) * F + j];
            g_c[j] = c;
        }
    }
}

// ---------------------------------------------------------------------------
// Build buckets: pos = deg[dst]++ (atomic), csr[dst*CAP + pos] = src.
// ---------------------------------------------------------------------------
__global__ void __launch_bounds__(256) build_kernel(const void* __restrict__ ei) {
    int base = (blockIdx.x * blockDim.x + threadIdx.x) * 4;
    if (base >= NEDGES) return;
    int s0, s1, s2, s3, d0, d1, d2, d3;
    if (g_is64) {
        const long long* ps = (const long long*)ei;
        const long long* pd = ps + NEDGES;
        s0 = (int)ps[base]; s1 = (int)ps[base + 1]; s2 = (int)ps[base + 2]; s3 = (int)ps[base + 3];
        d0 = (int)pd[base]; d1 = (int)pd[base + 1]; d2 = (int)pd[base + 2]; d3 = (int)pd[base + 3];
    } else {
        int4 sv = ((const int4*)((const int*)ei))[base >> 2];
        int4 dv = ((const int4*)((const int*)ei + NEDGES))[base >> 2];
        s0 = sv.x; s1 = sv.y; s2 = sv.z; s3 = sv.w;
        d0 = dv.x; d1 = dv.y; d2 = dv.z; d3 = dv.w;
    }
    int p0 = atomicAdd(&g_deg[d0], 1);
    int p1 = atomicAdd(&g_deg[d1], 1);
    int p2 = atomicAdd(&g_deg[d2], 1);
    int p3 = atomicAdd(&g_deg[d3], 1);
    g_csr[d0 * CAP + p0] = s0;
    g_csr[d1 * CAP + p1] = s1;
    g_csr[d2 * CAP + p2] = s2;
    g_csr[d3 * CAP + p3] = s3;
}

// ---------------------------------------------------------------------------
// Gather: one warp per dst node, fp32 accumulation over fp16 feat rows
// (X16 cols 0..127). Writes S (cols 128..255) and deg*feat (cols 256..383)
// back into X16 as fp16. Reads and writes touch disjoint column ranges.
// ---------------------------------------------------------------------------
__device__ __forceinline__ void acc_h4(float4& acc, uint2 p) {
    __half2 h0 = *(__half2*)&p.x;
    __half2 h1 = *(__half2*)&p.y;
    float2 f0 = __half22float2(h0);
    float2 f1 = __half22float2(h1);
    acc.x += f0.x; acc.y += f0.y; acc.z += f1.x; acc.w += f1.y;
}
__device__ __forceinline__ uint2 pack_h4(float4 v) {
    __half2 h0 = __float22half2_rn(make_float2(v.x, v.y));
    __half2 h1 = __float22half2_rn(make_float2(v.z, v.w));
    uint2 p;
    p.x = *(unsigned*)&h0;
    p.y = *(unsigned*)&h1;
    return p;
}

__global__ void __launch_bounds__(256) gather_kernel() {
    int warp = (blockIdx.x * blockDim.x + threadIdx.x) >> 5;
    int lane = threadIdx.x & 31;
    if (warp >= NATOMS) return;

    const int* bucket = g_csr + warp * CAP;
    const uint2* f16 = (const uint2*)g_X16;        // row stride 96 uint2; feat = first 32
    int n = g_deg[warp];
    int j = 0;
    float4 acc = make_float4(0.f, 0.f, 0.f, 0.f);

    while (n - j >= 32) {
        int s = bucket[j + lane];
#pragma unroll
        for (int i = 0; i < 32; i += 8) {
            uint2 v[8];
#pragma unroll
            for (int q = 0; q < 8; ++q) {
                int sq = __shfl_sync(0xffffffffu, s, i + q);
                v[q] = __ldg(f16 + sq * 96 + lane);
            }
#pragma unroll
            for (int q = 0; q < 8; ++q) acc_h4(acc, v[q]);
        }
        j += 32;
    }
    if (j < n) {
        int rem = n - j;
        int s = (lane < rem) ? bucket[j + lane] : 0;
        for (int i = 0; i < rem; ++i) {
            int si = __shfl_sync(0xffffffffu, s, i);
            uint2 v = __ldg(f16 + si * 96 + lane);
            acc_h4(acc, v);
        }
    }
    // S -> cols 128..255
    ((uint2*)g_X16)[warp * 96 + 32 + lane] = pack_h4(acc);
    // deg * feat -> cols 256..383
    float d = (float)n;
    uint2 fv = __ldg(f16 + warp * 96 + lane);
    __half2 h0 = *(__half2*)&fv.x;
    __half2 h1 = *(__half2*)&fv.y;
    float2 f0 = __half22float2(h0);
    float2 f1 = __half22float2(h1);
    ((uint2*)g_X16)[warp * 96 + 64 + lane] =
        pack_h4(make_float4(f0.x * d, f0.y * d, f1.x * d, f1.y * d));
}

// ---------------------------------------------------------------------------
// Tensor-core GEMM: out[10000,128] = X16[.,384] @ W16[384,128] + deg*c + b_upd
// Block: 128 rows x 128 cols, 256 threads (8 warps, 4x2), warp = 32x64.
// BK=64 (6 chunks). mma.sync m16n8k16 f16*f16 -> f32.
// ---------------------------------------------------------------------------
__device__ __forceinline__ void ldsm_x4(uint32_t r[4], uint32_t addr) {
    asm volatile("ldmatrix.sync.aligned.m8n8.x4.shared.b16 {%0,%1,%2,%3}, [%4];"
                 : "=r"(r[0]), "=r"(r[1]), "=r"(r[2]), "=r"(r[3]) : "r"(addr));
}
__device__ __forceinline__ void ldsm_x4_t(uint32_t r[4], uint32_t addr) {
    asm volatile("ldmatrix.sync.aligned.m8n8.x4.trans.shared.b16 {%0,%1,%2,%3}, [%4];"
                 : "=r"(r[0]), "=r"(r[1]), "=r"(r[2]), "=r"(r[3]) : "r"(addr));
}
__device__ __forceinline__ void mma16816(float d[4], const uint32_t a[4],
                                         uint32_t b0, uint32_t b1) {
    asm volatile("mma.sync.aligned.m16n8k16.row.col.f32.f16.f16.f32 "
                 "{%0,%1,%2,%3}, {%4,%5,%6,%7}, {%8,%9}, {%0,%1,%2,%3};"
                 : "+f"(d[0]), "+f"(d[1]), "+f"(d[2]), "+f"(d[3])
                 : "r"(a[0]), "r"(a[1]), "r"(a[2]), "r"(a[3]), "r"(b0), "r"(b1));
}

__global__ void __launch_bounds__(256) out_gemm(const float* __restrict__ b_upd,
                                                float* __restrict__ out) {
    __shared__ __align__(16) __half Xs[128][72];    // pitch 144B: conflict-free ldmatrix
    __shared__ __align__(16) __half Ws[64][136];    // pitch 272B: conflict-free ldmatrix

    int tid  = threadIdx.x;
    int lane = tid & 31, wid = tid >> 5;
    int wm = wid >> 1;               // 0..3 -> rows wm*32
    int wn = wid & 1;                // 0..1 -> cols wn*64
    int bm = blockIdx.x * 128;

    float acc[2][8][4];
#pragma unroll
    for (int mt = 0; mt < 2; ++mt)
#pragma unroll
        for (int nt = 0; nt < 8; ++nt)
#pragma unroll
            for (int q = 0; q < 4; ++q) acc[mt][nt][q] = 0.f;

#pragma unroll 1
    for (int c = 0; c < 6; ++c) {
        // ---- Xs: 128 rows x 64 halves = 1024 uint4; 4 per thread ----
#pragma unroll
        for (int i = 0; i < 4; ++i) {
            int idx = tid + i * 256;
            int row = idx >> 3, seg = idx & 7;
            uint4 v = __ldg((const uint4*)g_X16 + (u64_t)(bm + row) * 48 + c * 8 + seg);
            *(uint4*)&Xs[row][seg * 8] = v;
        }
        // ---- Ws: 64 k-rows x 128 halves = 1024 uint4; 4 per thread ----
#pragma unroll
        for (int i = 0; i < 4; ++i) {
            int idx = tid + i * 256;
            int row = idx >> 4, seg = idx & 15;
            uint4 v = __ldg((const uint4*)g_W16 + (c * 64 + row) * 16 + seg);
            *(uint4*)&Ws[row][seg * 8] = v;
        }
        __syncthreads();

#pragma unroll
        for (int ks = 0; ks < 4; ++ks) {
            uint32_t a[2][4];
            int arow = wm * 32 + (lane & 15);
            int acol = ks * 16 + ((lane >> 4) << 3);
#pragma unroll
            for (int mt = 0; mt < 2; ++mt) {
                uint32_t addr = (uint32_t)__cvta_generic_to_shared(&Xs[arow + mt * 16][acol]);
                ldsm_x4(a[mt], addr);
            }
            uint32_t bfr[4][4];
            int krow = ks * 16 + (lane & 7) + (((lane >> 3) & 1) << 3);
            int noff = ((lane >> 4) << 3);
#pragma unroll
            for (int nt4 = 0; nt4 < 4; ++nt4) {
                uint32_t addr = (uint32_t)__cvta_generic_to_shared(&Ws[krow][wn * 64 + nt4 * 16 + noff]);
                ldsm_x4_t(bfr[nt4], addr);
            }
#pragma unroll
            for (int mt = 0; mt < 2; ++mt)
#pragma unroll
                for (int nt = 0; nt < 8; ++nt)
                    mma16816(acc[mt][nt], a[mt],
                             bfr[nt >> 1][(nt & 1) * 2], bfr[nt >> 1][(nt & 1) * 2 + 1]);
        }
        __syncthreads();
    }

    // ---- epilogue: + deg*c + b_upd ----
    int colbase = wn * 64 + (lane & 3) * 2;
    float2 cv[8], bv[8];
#pragma unroll
    for (int nt = 0; nt < 8; ++nt) {
        int col = colbase + nt * 8;
        cv[nt] = make_float2(g_c[col], g_c[col + 1]);
        bv[nt] = make_float2(__ldg(&b_upd[col]), __ldg(&b_upd[col + 1]));
    }
#pragma unroll
    for (int mt = 0; mt < 2; ++mt) {
        int row0 = bm + wm * 32 + mt * 16 + (lane >> 2);
        int row1 = row0 + 8;
        float d0 = (row0 < NATOMS) ? (float)g_deg[row0] : 0.f;
        float d1 = (row1 < NATOMS) ? (float)g_deg[row1] : 0.f;
#pragma unroll
        for (int nt = 0; nt < 8; ++nt) {
            int col = colbase + nt * 8;
            if (row0 < NATOMS) {
                float2 o;
                o.x = acc[mt][nt][0] + d0 * cv[nt].x + bv[nt].x;
                o.y = acc[mt][nt][1] + d0 * cv[nt].y + bv[nt].y;
                *(float2*)&out[row0 * F + col] = o;
            }
            if (row1 < NATOMS) {
                float2 o;
                o.x = acc[mt][nt][2] + d1 * cv[nt].x + bv[nt].x;
                o.y = acc[mt][nt][3] + d1 * cv[nt].y + bv[nt].y;
                *(float2*)&out[row1 * F + col] = o;
            }
        }
    }
}

// ---------------------------------------------------------------------------
extern "C" void kernel_launch(void* const* d_in, const int* in_sizes, int n_in,
                              void* d_out, int out_size) {
    const float* feat  = (const float*)d_in[0];
    const void*  ei    = d_in[1];
    const float* W_msg = (const float*)d_in[2];
    const float* b_msg = (const float*)d_in[3];
    const float* W_upd = (const float*)d_in[4];
    const float* b_upd = (const float*)d_in[5];
    float*       out   = (float*)d_out;

    pre_kernel<<<1250, 256>>>(feat, ei, W_msg, b_msg, W_upd);
    build_kernel<<<(NEDGES / 4 + 255) / 256, 256>>>(ei);
    gather_kernel<<<(NATOMS * 32 + 255) / 256, 256>>>();
    out_gemm<<<NPAD / 128, 256>>>(b_upd, out);
}

// round 11
// speedup vs baseline: 1.8632x; 1.0255x over previous
#include <cuda_runtime.h>
#include <cuda_fp16.h>
#include <stdint.h>

#define NATOMS 10000
#define NPAD   10112   // NATOMS rounded up to 64/128; tail rows zeroed
#define F      128
#define NEDGES 640000
#define CAP    256     // per-node bucket capacity (deg ~ Poisson(64); P(>256) ~ 1e-80)

typedef unsigned long long u64_t;

// Scratch (static; no allocations allowed)
__device__ __align__(16) __half g_X16[NPAD * 384];   // [feat | S | deg*feat] fp16
__device__ __align__(16) __half g_W16[384 * F];      // folded weights fp16 [k][n]
__device__ __align__(16) int    g_deg[NATOMS];       // in-degree (also fill cursor)
__device__ int   g_csr[NATOMS * CAP];                // src indices bucketed by dst
__device__ int   g_is64;                             // 1 if edge dtype is int64
__device__ float g_c[F];                             // b_msg @ Wu_bot (fp32)

// ---------------------------------------------------------------------------
// Fused pre-pass: feat->fp16 into X16 cols 0..127, zero tail rows, zero deg,
// dtype detect, weight fold (fp32 math -> fp16 store).
// Grid: 1250 x 256  (1250*256 = 320000 = NATOMS*F/4 float4s)
// ---------------------------------------------------------------------------
__global__ void __launch_bounds__(256) pre_kernel(const float* __restrict__ feat,
                                                  const void*  __restrict__ ei,
                                                  const float* __restrict__ W_msg,
                                                  const float* __restrict__ b_msg,
                                                  const float* __restrict__ W_upd) {
    int b = blockIdx.x, t = threadIdx.x;
    int gi = b * 256 + t;

    {   // fp32 -> fp16: float4 -> 4 halves, row-major into X16 (row stride 384)
        int row = gi >> 5, seg = gi & 31;
        float4 v = __ldg((const float4*)feat + gi);
        __half2 h0 = __float22half2_rn(make_float2(v.x, v.y));
        __half2 h1 = __float22half2_rn(make_float2(v.z, v.w));
        uint2 p;
        p.x = *(unsigned*)&h0;
        p.y = *(unsigned*)&h1;
        ((uint2*)g_X16)[row * 96 + seg] = p;         // 384 halves = 96 uint2 per row
    }
    // zero tail rows (rows 10000..10111, all 384 cols): 112*96 = 10752 uint2
    if (gi < 10752) ((uint2*)g_X16)[NATOMS * 96 + gi] = make_uint2(0u, 0u);
    if (gi < NATOMS) g_deg[gi] = 0;
    if (gi == 0) {
        const long long* p = (const long long*)ei;
        int is64 = 1;
        for (int k = 0; k < 8; ++k) {
            long long v = p[k];
            if (v < 0 || v >= NATOMS) { is64 = 0; break; }
        }
        g_is64 = is64;
    }

    int j = t & 127, half = t >> 7;
    if (b < 128) {
        int i = b;
        float acc = 0.f;
        if (half == 0) {
#pragma unroll 8
            for (int k = 0; k < 128; ++k)
                acc += W_msg[i * F + k] * W_upd[(128 + k) * F + j];          // Wt row i
            g_W16[(128 + i) * F + j] = __float2half(acc);
        } else {
#pragma unroll 8
            for (int k = 0; k < 128; ++k)
                acc += W_msg[(128 + i) * F + k] * W_upd[(128 + k) * F + j]; // Wb row i
            g_W16[(256 + i) * F + j] = __float2half(acc);
        }
    } else if (b == 128) {
        for (int r = half * 64; r < half * 64 + 64; ++r)
            g_W16[r * F + j] = __float2half(W_upd[r * F + j]);
        if (half == 0) {
            float c = 0.f;
#pragma unroll 8
            for (int k = 0; k < 128; ++k)
                c += b_msg[k] * W_upd[(128 + k) * F + j];
            g_c[j] = c;
        }
    }
}

// ---------------------------------------------------------------------------
// Build buckets: pos = deg[dst]++ (atomic), csr[dst*CAP + pos] = src.
// ---------------------------------------------------------------------------
__global__ void __launch_bounds__(256) build_kernel(const void* __restrict__ ei) {
    int base = (blockIdx.x * blockDim.x + threadIdx.x) * 4;
    if (base >= NEDGES) return;
    int s0, s1, s2, s3, d0, d1, d2, d3;
    if (g_is64) {
        const long long* ps = (const long long*)ei;
        const long long* pd = ps + NEDGES;
        s0 = (int)ps[base]; s1 = (int)ps[base + 1]; s2 = (int)ps[base + 2]; s3 = (int)ps[base + 3];
        d0 = (int)pd[base]; d1 = (int)pd[base + 1]; d2 = (int)pd[base + 2]; d3 = (int)pd[base + 3];
    } else {
        int4 sv = ((const int4*)((const int*)ei))[base >> 2];
        int4 dv = ((const int4*)((const int*)ei + NEDGES))[base >> 2];
        s0 = sv.x; s1 = sv.y; s2 = sv.z; s3 = sv.w;
        d0 = dv.x; d1 = dv.y; d2 = dv.z; d3 = dv.w;
    }
    int p0 = atomicAdd(&g_deg[d0], 1);
    int p1 = atomicAdd(&g_deg[d1], 1);
    int p2 = atomicAdd(&g_deg[d2], 1);
    int p3 = atomicAdd(&g_deg[d3], 1);
    g_csr[d0 * CAP + p0] = s0;
    g_csr[d1 * CAP + p1] = s1;
    g_csr[d2 * CAP + p2] = s2;
    g_csr[d3 * CAP + p3] = s3;
}

// ---------------------------------------------------------------------------
// Gather: one warp per dst node, fp32 accumulation over fp16 feat rows
// (X16 cols 0..127). Writes S (cols 128..255) and deg*feat (cols 256..383).
// ---------------------------------------------------------------------------
__device__ __forceinline__ void acc_h4(float4& acc, uint2 p) {
    __half2 h0 = *(__half2*)&p.x;
    __half2 h1 = *(__half2*)&p.y;
    float2 f0 = __half22float2(h0);
    float2 f1 = __half22float2(h1);
    acc.x += f0.x; acc.y += f0.y; acc.z += f1.x; acc.w += f1.y;
}
__device__ __forceinline__ uint2 pack_h4(float4 v) {
    __half2 h0 = __float22half2_rn(make_float2(v.x, v.y));
    __half2 h1 = __float22half2_rn(make_float2(v.z, v.w));
    uint2 p;
    p.x = *(unsigned*)&h0;
    p.y = *(unsigned*)&h1;
    return p;
}

__global__ void __launch_bounds__(256) gather_kernel() {
    int warp = (blockIdx.x * blockDim.x + threadIdx.x) >> 5;
    int lane = threadIdx.x & 31;
    if (warp >= NATOMS) return;

    const int* bucket = g_csr + warp * CAP;
    const uint2* f16 = (const uint2*)g_X16;        // row stride 96 uint2; feat = first 32
    int n = g_deg[warp];
    int j = 0;
    float4 acc = make_float4(0.f, 0.f, 0.f, 0.f);

    while (n - j >= 32) {
        int s = bucket[j + lane];
#pragma unroll
        for (int i = 0; i < 32; i += 8) {
            uint2 v[8];
#pragma unroll
            for (int q = 0; q < 8; ++q) {
                int sq = __shfl_sync(0xffffffffu, s, i + q);
                v[q] = __ldg(f16 + sq * 96 + lane);
            }
#pragma unroll
            for (int q = 0; q < 8; ++q) acc_h4(acc, v[q]);
        }
        j += 32;
    }
    if (j < n) {
        int rem = n - j;
        int s = (lane < rem) ? bucket[j + lane] : 0;
        for (int i = 0; i < rem; ++i) {
            int si = __shfl_sync(0xffffffffu, s, i);
            uint2 v = __ldg(f16 + si * 96 + lane);
            acc_h4(acc, v);
        }
    }
    // S -> cols 128..255
    ((uint2*)g_X16)[warp * 96 + 32 + lane] = pack_h4(acc);
    // deg * feat -> cols 256..383
    float d = (float)n;
    uint2 fv = __ldg(f16 + warp * 96 + lane);
    __half2 h0 = *(__half2*)&fv.x;
    __half2 h1 = *(__half2*)&fv.y;
    float2 f0 = __half22float2(h0);
    float2 f1 = __half22float2(h1);
    ((uint2*)g_X16)[warp * 96 + 64 + lane] =
        pack_h4(make_float4(f0.x * d, f0.y * d, f1.x * d, f1.y * d));
}

// ---------------------------------------------------------------------------
// Tensor-core GEMM: out[10000,128] = X16[.,384] @ W16[384,128] + deg*c + b_upd
// Block: 64 rows x 128 cols, 256 threads (8 warps, 2x4), warp = 32x32.
// Grid = 158 (~1 wave on 148 SMs). BK=64 (6 chunks), register-staged
// prefetch of chunk c+1 overlaps GMEM latency with the 32 MMAs of chunk c.
// ---------------------------------------------------------------------------
__device__ __forceinline__ void ldsm_x4(uint32_t r[4], uint32_t addr) {
    asm volatile("ldmatrix.sync.aligned.m8n8.x4.shared.b16 {%0,%1,%2,%3}, [%4];"
                 : "=r"(r[0]), "=r"(r[1]), "=r"(r[2]), "=r"(r[3]) : "r"(addr));
}
__device__ __forceinline__ void ldsm_x4_t(uint32_t r[4], uint32_t addr) {
    asm volatile("ldmatrix.sync.aligned.m8n8.x4.trans.shared.b16 {%0,%1,%2,%3}, [%4];"
                 : "=r"(r[0]), "=r"(r[1]), "=r"(r[2]), "=r"(r[3]) : "r"(addr));
}
__device__ __forceinline__ void mma16816(float d[4], const uint32_t a[4],
                                         uint32_t b0, uint32_t b1) {
    asm volatile("mma.sync.aligned.m16n8k16.row.col.f32.f16.f16.f32 "
                 "{%0,%1,%2,%3}, {%4,%5,%6,%7}, {%8,%9}, {%0,%1,%2,%3};"
                 : "+f"(d[0]), "+f"(d[1]), "+f"(d[2]), "+f"(d[3])
                 : "r"(a[0]), "r"(a[1]), "r"(a[2]), "r"(a[3]), "r"(b0), "r"(b1));
}

__global__ void __launch_bounds__(256) out_gemm(const float* __restrict__ b_upd,
                                                float* __restrict__ out) {
    __shared__ __align__(16) __half Xs[64][72];     // pitch 144B: conflict-free ldmatrix
    __shared__ __align__(16) __half Ws[64][136];    // pitch 272B: conflict-free ldmatrix

    int tid  = threadIdx.x;
    int lane = tid & 31, wid = tid >> 5;
    int wm = wid >> 2;               // 0..1 -> rows wm*32
    int wn = wid & 3;                // 0..3 -> cols wn*32
    int bm = blockIdx.x * 64;

    float acc[2][4][4];
#pragma unroll
    for (int mt = 0; mt < 2; ++mt)
#pragma unroll
        for (int nt = 0; nt < 4; ++nt)
#pragma unroll
            for (int q = 0; q < 4; ++q) acc[mt][nt][q] = 0.f;

    // register staging for prefetch
    uint4 xv[2], wv[4];
    auto loadXW = [&](int c) {
#pragma unroll
        for (int i = 0; i < 2; ++i) {                   // Xs: 64 rows x 8 uint4
            int idx = tid + i * 256;
            int row = idx >> 3, seg = idx & 7;
            xv[i] = __ldg((const uint4*)g_X16 + (u64_t)(bm + row) * 48 + c * 8 + seg);
        }
#pragma unroll
        for (int i = 0; i < 4; ++i) {                   // Ws: 64 k-rows x 16 uint4
            int idx = tid + i * 256;
            int row = idx >> 4, seg = idx & 15;
            wv[i] = __ldg((const uint4*)g_W16 + (c * 64 + row) * 16 + seg);
        }
    };
    auto storeXW = [&]() {
#pragma unroll
        for (int i = 0; i < 2; ++i) {
            int idx = tid + i * 256;
            int row = idx >> 3, seg = idx & 7;
            *(uint4*)&Xs[row][seg * 8] = xv[i];
        }
#pragma unroll
        for (int i = 0; i < 4; ++i) {
            int idx = tid + i * 256;
            int row = idx >> 4, seg = idx & 15;
            *(uint4*)&Ws[row][seg * 8] = wv[i];
        }
    };

    loadXW(0);
#pragma unroll 1
    for (int c = 0; c < 6; ++c) {
        storeXW();
        __syncthreads();
        if (c < 5) loadXW(c + 1);                       // prefetch hidden by MMAs below
#pragma unroll
        for (int ks = 0; ks < 4; ++ks) {
            uint32_t a[2][4];
            int arow = wm * 32 + (lane & 15);
            int acol = ks * 16 + ((lane >> 4) << 3);
#pragma unroll
            for (int mt = 0; mt < 2; ++mt) {
                uint32_t addr = (uint32_t)__cvta_generic_to_shared(&Xs[arow + mt * 16][acol]);
                ldsm_x4(a[mt], addr);
            }
            uint32_t bfr[2][4];
            int krow = ks * 16 + (lane & 7) + (((lane >> 3) & 1) << 3);
            int noff = ((lane >> 4) << 3);
#pragma unroll
            for (int nt4 = 0; nt4 < 2; ++nt4) {
                uint32_t addr = (uint32_t)__cvta_generic_to_shared(&Ws[krow][wn * 32 + nt4 * 16 + noff]);
                ldsm_x4_t(bfr[nt4], addr);
            }
#pragma unroll
            for (int mt = 0; mt < 2; ++mt)
#pragma unroll
                for (int nt = 0; nt < 4; ++nt)
                    mma16816(acc[mt][nt], a[mt],
                             bfr[nt >> 1][(nt & 1) * 2], bfr[nt >> 1][(nt & 1) * 2 + 1]);
        }
        __syncthreads();
    }

    // ---- epilogue: + deg*c + b_upd ----
    int colbase = wn * 32 + (lane & 3) * 2;
    float2 cv[4], bv[4];
#pragma unroll
    for (int nt = 0; nt < 4; ++nt) {
        int col = colbase + nt * 8;
        cv[nt] = make_float2(g_c[col], g_c[col + 1]);
        bv[nt] = make_float2(__ldg(&b_upd[col]), __ldg(&b_upd[col + 1]));
    }
#pragma unroll
    for (int mt = 0; mt < 2; ++mt) {
        int row0 = bm + wm * 32 + mt * 16 + (lane >> 2);
        int row1 = row0 + 8;
        float d0 = (row0 < NATOMS) ? (float)g_deg[row0] : 0.f;
        float d1 = (row1 < NATOMS) ? (float)g_deg[row1] : 0.f;
#pragma unroll
        for (int nt = 0; nt < 4; ++nt) {
            int col = colbase + nt * 8;
            if (row0 < NATOMS) {
                float2 o;
                o.x = acc[mt][nt][0] + d0 * cv[nt].x + bv[nt].x;
                o.y = acc[mt][nt][1] + d0 * cv[nt].y + bv[nt].y;
                *(float2*)&out[row0 * F + col] = o;
            }
            if (row1 < NATOMS) {
                float2 o;
                o.x = acc[mt][nt][2] + d1 * cv[nt].x + bv[nt].x;
                o.y = acc[mt][nt][3] + d1 * cv[nt].y + bv[nt].y;
                *(float2*)&out[row1 * F + col] = o;
            }
        }
    }
}

// ---------------------------------------------------------------------------
extern "C" void kernel_launch(void* const* d_in, const int* in_sizes, int n_in,
                              void* d_out, int out_size) {
    const float* feat  = (const float*)d_in[0];
    const void*  ei    = d_in[1];
    const float* W_msg = (const float*)d_in[2];
    const float* b_msg = (const float*)d_in[3];
    const float* W_upd = (const float*)d_in[4];
    const float* b_upd = (const float*)d_in[5];
    float*       out   = (float*)d_out;

    pre_kernel<<<1250, 256>>>(feat, ei, W_msg, b_msg, W_upd);
    build_kernel<<<(NEDGES / 4 + 255) / 256, 256>>>(ei);
    gather_kernel<<<(NATOMS * 32 + 255) / 256, 256>>>();
    out_gemm<<<NPAD / 64, 256>>>(b_upd, out);
}

// round 12
// speedup vs baseline: 1.9414x; 1.0420x over previous
#include <cuda_runtime.h>
#include <cuda_fp16.h>
#include <stdint.h>

#define NATOMS 10000
#define NPAD   10112   // NATOMS rounded up to 64; tail rows zeroed
#define F      128
#define NEDGES 640000
#define CAP    256     // per-node bucket capacity (deg ~ Poisson(64); P(>256) ~ 1e-80)

typedef unsigned long long u64_t;

// Scratch (static; no allocations allowed).
// NOTE: g_deg is zero at module load and re-zeroed at the END of out_gemm each
// call, so prebuild_kernel can start its atomic histogram immediately.
__device__ __align__(16) __half g_X16[NPAD * 384];   // [feat | S | deg*feat] fp16
__device__ __align__(16) __half g_W16[384 * F];      // folded weights fp16 [k][n]
__device__ __align__(16) int    g_deg[NATOMS];       // in-degree (also fill cursor)
__device__ int   g_csr[NATOMS * CAP];                // src indices bucketed by dst
__device__ float g_c[F];                             // b_msg @ Wu_bot (fp32)

// ---------------------------------------------------------------------------
// Fused pre+build: fp16 convert (all 1250 blocks), edge-bucket build
// (blocks 0..624, 4 edges/thread), weight fold (blocks 625..753).
// ---------------------------------------------------------------------------
__global__ void __launch_bounds__(256) prebuild_kernel(const float* __restrict__ feat,
                                                       const void*  __restrict__ ei,
                                                       const float* __restrict__ W_msg,
                                                       const float* __restrict__ b_msg,
                                                       const float* __restrict__ W_upd) {
    int b = blockIdx.x, t = threadIdx.x;
    int gi = b * 256 + t;

    {   // fp32 -> fp16: float4 -> 4 halves, row-major into X16 (row stride 384)
        int row = gi >> 5, seg = gi & 31;
        float4 v = __ldg((const float4*)feat + gi);
        __half2 h0 = __float22half2_rn(make_float2(v.x, v.y));
        __half2 h1 = __float22half2_rn(make_float2(v.z, v.w));
        uint2 p;
        p.x = *(unsigned*)&h0;
        p.y = *(unsigned*)&h1;
        ((uint2*)g_X16)[row * 96 + seg] = p;         // 384 halves = 96 uint2 per row
    }
    // zero tail rows (rows 10000..10111, all 384 cols): 112*96 = 10752 uint2
    if (gi < 10752) ((uint2*)g_X16)[NATOMS * 96 + gi] = make_uint2(0u, 0u);

    if (b < 625) {
        // ---- edge-bucket build: 4 edges/thread (ILP-4 atomic chains) ----
        __shared__ int s_is64;
        if (t == 0) {
            const long long* p = (const long long*)ei;
            int is64 = 1;
            for (int k = 0; k < 8; ++k) {
                long long v = p[k];
                if (v < 0 || v >= NATOMS) { is64 = 0; break; }
            }
            s_is64 = is64;
        }
        __syncthreads();
        int base = (b * 256 + t) * 4;                // 625*256*4 == NEDGES exactly
        int s0, s1, s2, s3, d0, d1, d2, d3;
        if (s_is64) {
            const long long* ps = (const long long*)ei;
            const long long* pd = ps + NEDGES;
            s0 = (int)ps[base]; s1 = (int)ps[base + 1]; s2 = (int)ps[base + 2]; s3 = (int)ps[base + 3];
            d0 = (int)pd[base]; d1 = (int)pd[base + 1]; d2 = (int)pd[base + 2]; d3 = (int)pd[base + 3];
        } else {
            int4 sv = ((const int4*)((const int*)ei))[base >> 2];
            int4 dv = ((const int4*)((const int*)ei + NEDGES))[base >> 2];
            s0 = sv.x; s1 = sv.y; s2 = sv.z; s3 = sv.w;
            d0 = dv.x; d1 = dv.y; d2 = dv.z; d3 = dv.w;
        }
        int p0 = atomicAdd(&g_deg[d0], 1);
        int p1 = atomicAdd(&g_deg[d1], 1);
        int p2 = atomicAdd(&g_deg[d2], 1);
        int p3 = atomicAdd(&g_deg[d3], 1);
        g_csr[d0 * CAP + p0] = s0;
        g_csr[d1 * CAP + p1] = s1;
        g_csr[d2 * CAP + p2] = s2;
        g_csr[d3 * CAP + p3] = s3;
    } else if (b < 754) {
        // ---- weight fold ----
        int i = b - 625;                              // 0..128
        int j = t & 127, half = t >> 7;
        if (i < 128) {
            float acc = 0.f;
            if (half == 0) {
#pragma unroll 8
                for (int k = 0; k < 128; ++k)
                    acc += W_msg[i * F + k] * W_upd[(128 + k) * F + j];          // Wt row i
                g_W16[(128 + i) * F + j] = __float2half(acc);
            } else {
#pragma unroll 8
                for (int k = 0; k < 128; ++k)
                    acc += W_msg[(128 + i) * F + k] * W_upd[(128 + k) * F + j]; // Wb row i
                g_W16[(256 + i) * F + j] = __float2half(acc);
            }
        } else {
            for (int r = half * 64; r < half * 64 + 64; ++r)
                g_W16[r * F + j] = __float2half(W_upd[r * F + j]);
            if (half == 0) {
                float c = 0.f;
#pragma unroll 8
                for (int k = 0; k < 128; ++k)
                    c += b_msg[k] * W_upd[(128 + k) * F + j];
                g_c[j] = c;
            }
        }
    }
}

// ---------------------------------------------------------------------------
// Gather: one warp per dst node, fp32 accumulation over fp16 feat rows
// (X16 cols 0..127). Writes S (cols 128..255) and deg*feat (cols 256..383).
// ---------------------------------------------------------------------------
__device__ __forceinline__ void acc_h4(float4& acc, uint2 p) {
    __half2 h0 = *(__half2*)&p.x;
    __half2 h1 = *(__half2*)&p.y;
    float2 f0 = __half22float2(h0);
    float2 f1 = __half22float2(h1);
    acc.x += f0.x; acc.y += f0.y; acc.z += f1.x; acc.w += f1.y;
}
__device__ __forceinline__ uint2 pack_h4(float4 v) {
    __half2 h0 = __float22half2_rn(make_float2(v.x, v.y));
    __half2 h1 = __float22half2_rn(make_float2(v.z, v.w));
    uint2 p;
    p.x = *(unsigned*)&h0;
    p.y = *(unsigned*)&h1;
    return p;
}

__global__ void __launch_bounds__(256) gather_kernel() {
    int warp = (blockIdx.x * blockDim.x + threadIdx.x) >> 5;
    int lane = threadIdx.x & 31;
    if (warp >= NATOMS) return;

    const int* bucket = g_csr + warp * CAP;
    const uint2* f16 = (const uint2*)g_X16;        // row stride 96 uint2; feat = first 32
    int n = g_deg[warp];
    int j = 0;
    float4 acc = make_float4(0.f, 0.f, 0.f, 0.f);

    while (n - j >= 32) {
        int s = bucket[j + lane];
#pragma unroll
        for (int i = 0; i < 32; i += 8) {
            uint2 v[8];
#pragma unroll
            for (int q = 0; q < 8; ++q) {
                int sq = __shfl_sync(0xffffffffu, s, i + q);
                v[q] = __ldg(f16 + sq * 96 + lane);
            }
#pragma unroll
            for (int q = 0; q < 8; ++q) acc_h4(acc, v[q]);
        }
        j += 32;
    }
    if (j < n) {
        int rem = n - j;
        int s = (lane < rem) ? bucket[j + lane] : 0;
        for (int i = 0; i < rem; ++i) {
            int si = __shfl_sync(0xffffffffu, s, i);
            uint2 v = __ldg(f16 + si * 96 + lane);
            acc_h4(acc, v);
        }
    }
    // S -> cols 128..255
    ((uint2*)g_X16)[warp * 96 + 32 + lane] = pack_h4(acc);
    // deg * feat -> cols 256..383
    float d = (float)n;
    uint2 fv = __ldg(f16 + warp * 96 + lane);
    __half2 h0 = *(__half2*)&fv.x;
    __half2 h1 = *(__half2*)&fv.y;
    float2 f0 = __half22float2(h0);
    float2 f1 = __half22float2(h1);
    ((uint2*)g_X16)[warp * 96 + 64 + lane] =
        pack_h4(make_float4(f0.x * d, f0.y * d, f1.x * d, f1.y * d));
}

// ---------------------------------------------------------------------------
// Tensor-core GEMM with double-buffered smem: one __syncthreads per K-chunk.
// Block: 64 rows x 128 cols, 256 threads (8 warps, 2x4), warp = 32x32.
// Grid = 158. At the end each block zeroes its own g_deg rows (invariant for
// the next invocation's prebuild histogram).
// Dynamic smem layout (halves): Xs0@0(4608) Ws0@4608(8704) Xs1@13312 Ws1@17920
// ---------------------------------------------------------------------------
__device__ __forceinline__ void ldsm_x4(uint32_t r[4], uint32_t addr) {
    asm volatile("ldmatrix.sync.aligned.m8n8.x4.shared.b16 {%0,%1,%2,%3}, [%4];"
                 : "=r"(r[0]), "=r"(r[1]), "=r"(r[2]), "=r"(r[3]) : "r"(addr));
}
__device__ __forceinline__ void ldsm_x4_t(uint32_t r[4], uint32_t addr) {
    asm volatile("ldmatrix.sync.aligned.m8n8.x4.trans.shared.b16 {%0,%1,%2,%3}, [%4];"
                 : "=r"(r[0]), "=r"(r[1]), "=r"(r[2]), "=r"(r[3]) : "r"(addr));
}
__device__ __forceinline__ void mma16816(float d[4], const uint32_t a[4],
                                         uint32_t b0, uint32_t b1) {
    asm volatile("mma.sync.aligned.m16n8k16.row.col.f32.f16.f16.f32 "
                 "{%0,%1,%2,%3}, {%4,%5,%6,%7}, {%8,%9}, {%0,%1,%2,%3};"
                 : "+f"(d[0]), "+f"(d[1]), "+f"(d[2]), "+f"(d[3])
                 : "r"(a[0]), "r"(a[1]), "r"(a[2]), "r"(a[3]), "r"(b0), "r"(b1));
}

#define XPITCH 72
#define WPITCH 136
#define GEMM_SMEM_BYTES ((4608 + 8704) * 2 * 2)

__global__ void __launch_bounds__(256) out_gemm(const float* __restrict__ b_upd,
                                                float* __restrict__ out) {
    extern __shared__ __align__(16) __half smem[];
    __half* XsBuf[2] = { smem,         smem + 13312 };
    __half* WsBuf[2] = { smem + 4608,  smem + 17920 };

    int tid  = threadIdx.x;
    int lane = tid & 31, wid = tid >> 5;
    int wm = wid >> 2;               // 0..1 -> rows wm*32
    int wn = wid & 3;                // 0..3 -> cols wn*32
    int bm = blockIdx.x * 64;

    float acc[2][4][4];
#pragma unroll
    for (int mt = 0; mt < 2; ++mt)
#pragma unroll
        for (int nt = 0; nt < 4; ++nt)
#pragma unroll
            for (int q = 0; q < 4; ++q) acc[mt][nt][q] = 0.f;

    // register staging for prefetch
    uint4 xv[2], wv[4];
    auto loadXW = [&](int c) {
#pragma unroll
        for (int i = 0; i < 2; ++i) {                   // Xs: 64 rows x 8 uint4
            int idx = tid + i * 256;
            int row = idx >> 3, seg = idx & 7;
            xv[i] = __ldg((const uint4*)g_X16 + (u64_t)(bm + row) * 48 + c * 8 + seg);
        }
#pragma unroll
        for (int i = 0; i < 4; ++i) {                   // Ws: 64 k-rows x 16 uint4
            int idx = tid + i * 256;
            int row = idx >> 4, seg = idx & 15;
            wv[i] = __ldg((const uint4*)g_W16 + (c * 64 + row) * 16 + seg);
        }
    };
    auto storeXW = [&](int buf) {
        __half* Xp = XsBuf[buf];
        __half* Wp = WsBuf[buf];
#pragma unroll
        for (int i = 0; i < 2; ++i) {
            int idx = tid + i * 256;
            int row = idx >> 3, seg = idx & 7;
            *(uint4*)&Xp[row * XPITCH + seg * 8] = xv[i];
        }
#pragma unroll
        for (int i = 0; i < 4; ++i) {
            int idx = tid + i * 256;
            int row = idx >> 4, seg = idx & 15;
            *(uint4*)&Wp[row * WPITCH + seg * 8] = wv[i];
        }
    };

    loadXW(0);
    storeXW(0);
#pragma unroll 1
    for (int c = 0; c < 6; ++c) {
        __syncthreads();                                 // buf c&1 ready for all
        if (c < 5) loadXW(c + 1);                        // LDG prefetch (regs)
        const __half* Xp = XsBuf[c & 1];
        const __half* Wp = WsBuf[c & 1];
#pragma unroll
        for (int ks = 0; ks < 4; ++ks) {
            uint32_t a[2][4];
            int arow = wm * 32 + (lane & 15);
            int acol = ks * 16 + ((lane >> 4) << 3);
#pragma unroll
            for (int mt = 0; mt < 2; ++mt) {
                uint32_t addr = (uint32_t)__cvta_generic_to_shared(
                    &Xp[(arow + mt * 16) * XPITCH + acol]);
                ldsm_x4(a[mt], addr);
            }
            uint32_t bfr[2][4];
            int krow = ks * 16 + (lane & 7) + (((lane >> 3) & 1) << 3);
            int noff = ((lane >> 4) << 3);
#pragma unroll
            for (int nt4 = 0; nt4 < 2; ++nt4) {
                uint32_t addr = (uint32_t)__cvta_generic_to_shared(
                    &Wp[krow * WPITCH + wn * 32 + nt4 * 16 + noff]);
                ldsm_x4_t(bfr[nt4], addr);
            }
#pragma unroll
            for (int mt = 0; mt < 2; ++mt)
#pragma unroll
                for (int nt = 0; nt < 4; ++nt)
                    mma16816(acc[mt][nt], a[mt],
                             bfr[nt >> 1][(nt & 1) * 2], bfr[nt >> 1][(nt & 1) * 2 + 1]);
        }
        if (c < 5) storeXW((c + 1) & 1);                 // other buffer: no conflict
    }

    // ---- epilogue: + deg*c + b_upd ----
    int colbase = wn * 32 + (lane & 3) * 2;
    float2 cv[4], bv[4];
#pragma unroll
    for (int nt = 0; nt < 4; ++nt) {
        int col = colbase + nt * 8;
        cv[nt] = make_float2(g_c[col], g_c[col + 1]);
        bv[nt] = make_float2(__ldg(&b_upd[col]), __ldg(&b_upd[col + 1]));
    }
#pragma unroll
    for (int mt = 0; mt < 2; ++mt) {
        int row0 = bm + wm * 32 + mt * 16 + (lane >> 2);
        int row1 = row0 + 8;
        float d0 = (row0 < NATOMS) ? (float)g_deg[row0] : 0.f;
        float d1 = (row1 < NATOMS) ? (float)g_deg[row1] : 0.f;
#pragma unroll
        for (int nt = 0; nt < 4; ++nt) {
            int col = colbase + nt * 8;
            if (row0 < NATOMS) {
                float2 o;
                o.x = acc[mt][nt][0] + d0 * cv[nt].x + bv[nt].x;
                o.y = acc[mt][nt][1] + d0 * cv[nt].y + bv[nt].y;
                *(float2*)&out[row0 * F + col] = o;
            }
            if (row1 < NATOMS) {
                float2 o;
                o.x = acc[mt][nt][2] + d1 * cv[nt].x + bv[nt].x;
                o.y = acc[mt][nt][3] + d1 * cv[nt].y + bv[nt].y;
                *(float2*)&out[row1 * F + col] = o;
            }
        }
    }

    // ---- restore invariant: zero this block's g_deg rows for the next call ----
    __syncthreads();                                     // all epilogue reads done
    if (tid < 64) {
        int r = bm + tid;
        if (r < NATOMS) g_deg[r] = 0;
    }
}

// ---------------------------------------------------------------------------
extern "C" void kernel_launch(void* const* d_in, const int* in_sizes, int n_in,
                              void* d_out, int out_size) {
    const float* feat  = (const float*)d_in[0];
    const void*  ei    = d_in[1];
    const float* W_msg = (const float*)d_in[2];
    const float* b_msg = (const float*)d_in[3];
    const float* W_upd = (const float*)d_in[4];
    const float* b_upd = (const float*)d_in[5];
    float*       out   = (float*)d_out;

    static int configured = 0;
    if (!configured) {
        cudaFuncSetAttribute(out_gemm, cudaFuncAttributeMaxDynamicSharedMemorySize,
                             GEMM_SMEM_BYTES);
        configured = 1;
    }

    prebuild_kernel<<<1250, 256>>>(feat, ei, W_msg, b_msg, W_upd);
    gather_kernel<<<(NATOMS * 32 + 255) / 256, 256>>>();
    out_gemm<<<NPAD / 64, 256, GEMM_SMEM_BYTES>>>(b_upd, out);
}

// round 13
// speedup vs baseline: 1.9644x; 1.0119x over previous
#include <cuda_runtime.h>
#include <cuda_fp16.h>
#include <stdint.h>

#define NATOMS 10000
#define NPAD   10112   // NATOMS rounded up to 64; tail rows zeroed
#define F      128
#define NEDGES 640000
#define CAP    256     // per-node bucket capacity (deg ~ Poisson(64); P(>256) ~ 1e-80)

typedef unsigned long long u64_t;

// Scratch (static; no allocations allowed).
// NOTE: g_deg is zero at module load and re-zeroed at the END of out_gemm each
// call, so prebuild_kernel can start its atomic histogram immediately.
__device__ __align__(16) __half g_X16[NPAD * 384];   // [feat | S | deg*feat] fp16
__device__ __align__(16) __half g_W16[384 * F];      // folded weights fp16 [k][n]
__device__ __align__(16) int    g_deg[NATOMS];       // in-degree (also fill cursor)
__device__ int   g_csr[NATOMS * CAP];                // src indices bucketed by dst
__device__ float g_c[F];                             // b_msg @ Wu_bot (fp32)

// ---------------------------------------------------------------------------
// Fused pre+build: every block does fp16 convert AND 2 edges/thread of the
// bucket build (max chip-wide atomic concurrency); blocks 625..753 also fold
// weights. 1250*256*2 == NEDGES exactly.
// ---------------------------------------------------------------------------
__global__ void __launch_bounds__(256) prebuild_kernel(const float* __restrict__ feat,
                                                       const void*  __restrict__ ei,
                                                       const float* __restrict__ W_msg,
                                                       const float* __restrict__ b_msg,
                                                       const float* __restrict__ W_upd) {
    int b = blockIdx.x, t = threadIdx.x;
    int gi = b * 256 + t;

    // ---- dtype detect (per block, cheap) ----
    __shared__ int s_is64;
    if (t == 0) {
        const long long* p = (const long long*)ei;
        int is64 = 1;
        for (int k = 0; k < 8; ++k) {
            long long v = p[k];
            if (v < 0 || v >= NATOMS) { is64 = 0; break; }
        }
        s_is64 = is64;
    }

    {   // fp32 -> fp16: float4 -> 4 halves, row-major into X16 (row stride 384)
        int row = gi >> 5, seg = gi & 31;
        float4 v = __ldg((const float4*)feat + gi);
        __half2 h0 = __float22half2_rn(make_float2(v.x, v.y));
        __half2 h1 = __float22half2_rn(make_float2(v.z, v.w));
        uint2 p;
        p.x = *(unsigned*)&h0;
        p.y = *(unsigned*)&h1;
        ((uint2*)g_X16)[row * 96 + seg] = p;         // 384 halves = 96 uint2 per row
    }
    // zero tail rows (rows 10000..10111, all 384 cols): 112*96 = 10752 uint2
    if (gi < 10752) ((uint2*)g_X16)[NATOMS * 96 + gi] = make_uint2(0u, 0u);

    __syncthreads();
    // ---- edge-bucket build: 2 edges/thread, all blocks ----
    {
        int base = gi * 2;
        int s0, s1, d0, d1;
        if (s_is64) {
            const long long* ps = (const long long*)ei;
            const long long* pd = ps + NEDGES;
            s0 = (int)ps[base]; s1 = (int)ps[base + 1];
            d0 = (int)pd[base]; d1 = (int)pd[base + 1];
        } else {
            int2 sv = ((const int2*)((const int*)ei))[gi];
            int2 dv = ((const int2*)((const int*)ei + NEDGES))[gi];
            s0 = sv.x; s1 = sv.y;
            d0 = dv.x; d1 = dv.y;
        }
        int p0 = atomicAdd(&g_deg[d0], 1);
        int p1 = atomicAdd(&g_deg[d1], 1);
        g_csr[d0 * CAP + p0] = s0;
        g_csr[d1 * CAP + p1] = s1;
    }

    if (b >= 625 && b < 754) {
        // ---- weight fold ----
        int i = b - 625;                              // 0..128
        int j = t & 127, half = t >> 7;
        if (i < 128) {
            float acc = 0.f;
            if (half == 0) {
#pragma unroll 8
                for (int k = 0; k < 128; ++k)
                    acc += W_msg[i * F + k] * W_upd[(128 + k) * F + j];          // Wt row i
                g_W16[(128 + i) * F + j] = __float2half(acc);
            } else {
#pragma unroll 8
                for (int k = 0; k < 128; ++k)
                    acc += W_msg[(128 + i) * F + k] * W_upd[(128 + k) * F + j]; // Wb row i
                g_W16[(256 + i) * F + j] = __float2half(acc);
            }
        } else {
            for (int r = half * 64; r < half * 64 + 64; ++r)
                g_W16[r * F + j] = __float2half(W_upd[r * F + j]);
            if (half == 0) {
                float c = 0.f;
#pragma unroll 8
                for (int k = 0; k < 128; ++k)
                    c += b_msg[k] * W_upd[(128 + k) * F + j];
                g_c[j] = c;
            }
        }
    }
}

// ---------------------------------------------------------------------------
// Gather: one warp per dst node, fp32 accumulation over fp16 feat rows
// (X16 cols 0..127). Writes S (cols 128..255) and deg*feat (cols 256..383).
// ---------------------------------------------------------------------------
__device__ __forceinline__ void acc_h4(float4& acc, uint2 p) {
    __half2 h0 = *(__half2*)&p.x;
    __half2 h1 = *(__half2*)&p.y;
    float2 f0 = __half22float2(h0);
    float2 f1 = __half22float2(h1);
    acc.x += f0.x; acc.y += f0.y; acc.z += f1.x; acc.w += f1.y;
}
__device__ __forceinline__ uint2 pack_h4(float4 v) {
    __half2 h0 = __float22half2_rn(make_float2(v.x, v.y));
    __half2 h1 = __float22half2_rn(make_float2(v.z, v.w));
    uint2 p;
    p.x = *(unsigned*)&h0;
    p.y = *(unsigned*)&h1;
    return p;
}

__global__ void __launch_bounds__(256) gather_kernel() {
    int warp = (blockIdx.x * blockDim.x + threadIdx.x) >> 5;
    int lane = threadIdx.x & 31;
    if (warp >= NATOMS) return;

    const int* bucket = g_csr + warp * CAP;
    const uint2* f16 = (const uint2*)g_X16;        // row stride 96 uint2; feat = first 32
    int n = g_deg[warp];
    int j = 0;
    float4 acc = make_float4(0.f, 0.f, 0.f, 0.f);

    while (n - j >= 32) {
        int s = bucket[j + lane];
#pragma unroll
        for (int i = 0; i < 32; i += 8) {
            uint2 v[8];
#pragma unroll
            for (int q = 0; q < 8; ++q) {
                int sq = __shfl_sync(0xffffffffu, s, i + q);
                v[q] = __ldg(f16 + sq * 96 + lane);
            }
#pragma unroll
            for (int q = 0; q < 8; ++q) acc_h4(acc, v[q]);
        }
        j += 32;
    }
    if (j < n) {
        int rem = n - j;
        int s = (lane < rem) ? bucket[j + lane] : 0;
        for (int i = 0; i < rem; ++i) {
            int si = __shfl_sync(0xffffffffu, s, i);
            uint2 v = __ldg(f16 + si * 96 + lane);
            acc_h4(acc, v);
        }
    }
    // S -> cols 128..255
    ((uint2*)g_X16)[warp * 96 + 32 + lane] = pack_h4(acc);
    // deg * feat -> cols 256..383
    float d = (float)n;
    uint2 fv = __ldg(f16 + warp * 96 + lane);
    __half2 h0 = *(__half2*)&fv.x;
    __half2 h1 = *(__half2*)&fv.y;
    float2 f0 = __half22float2(h0);
    float2 f1 = __half22float2(h1);
    ((uint2*)g_X16)[warp * 96 + 64 + lane] =
        pack_h4(make_float4(f0.x * d, f0.y * d, f1.x * d, f1.y * d));
}

// ---------------------------------------------------------------------------
// Tensor-core GEMM with double-buffered smem: one __syncthreads per K-chunk.
// Block: 64 rows x 128 cols, 256 threads (8 warps, 2x4), warp = 32x32.
// Grid = 158. At the end each block zeroes its own g_deg rows (invariant for
// the next invocation's prebuild histogram).
// ---------------------------------------------------------------------------
__device__ __forceinline__ void ldsm_x4(uint32_t r[4], uint32_t addr) {
    asm volatile("ldmatrix.sync.aligned.m8n8.x4.shared.b16 {%0,%1,%2,%3}, [%4];"
                 : "=r"(r[0]), "=r"(r[1]), "=r"(r[2]), "=r"(r[3]) : "r"(addr));
}
__device__ __forceinline__ void ldsm_x4_t(uint32_t r[4], uint32_t addr) {
    asm volatile("ldmatrix.sync.aligned.m8n8.x4.trans.shared.b16 {%0,%1,%2,%3}, [%4];"
                 : "=r"(r[0]), "=r"(r[1]), "=r"(r[2]), "=r"(r[3]) : "r"(addr));
}
__device__ __forceinline__ void mma16816(float d[4], const uint32_t a[4],
                                         uint32_t b0, uint32_t b1) {
    asm volatile("mma.sync.aligned.m16n8k16.row.col.f32.f16.f16.f32 "
                 "{%0,%1,%2,%3}, {%4,%5,%6,%7}, {%8,%9}, {%0,%1,%2,%3};"
                 : "+f"(d[0]), "+f"(d[1]), "+f"(d[2]), "+f"(d[3])
                 : "r"(a[0]), "r"(a[1]), "r"(a[2]), "r"(a[3]), "r"(b0), "r"(b1));
}

#define XPITCH 72
#define WPITCH 136
#define GEMM_SMEM_BYTES ((4608 + 8704) * 2 * 2)

__global__ void __launch_bounds__(256) out_gemm(const float* __restrict__ b_upd,
                                                float* __restrict__ out) {
    extern __shared__ __align__(16) __half smem[];
    __half* XsBuf[2] = { smem,         smem + 13312 };
    __half* WsBuf[2] = { smem + 4608,  smem + 17920 };

    int tid  = threadIdx.x;
    int lane = tid & 31, wid = tid >> 5;
    int wm = wid >> 2;               // 0..1 -> rows wm*32
    int wn = wid & 3;                // 0..3 -> cols wn*32
    int bm = blockIdx.x * 64;

    float acc[2][4][4];
#pragma unroll
    for (int mt = 0; mt < 2; ++mt)
#pragma unroll
        for (int nt = 0; nt < 4; ++nt)
#pragma unroll
            for (int q = 0; q < 4; ++q) acc[mt][nt][q] = 0.f;

    // register staging for prefetch
    uint4 xv[2], wv[4];
    auto loadXW = [&](int c) {
#pragma unroll
        for (int i = 0; i < 2; ++i) {                   // Xs: 64 rows x 8 uint4
            int idx = tid + i * 256;
            int row = idx >> 3, seg = idx & 7;
            xv[i] = __ldg((const uint4*)g_X16 + (u64_t)(bm + row) * 48 + c * 8 + seg);
        }
#pragma unroll
        for (int i = 0; i < 4; ++i) {                   // Ws: 64 k-rows x 16 uint4
            int idx = tid + i * 256;
            int row = idx >> 4, seg = idx & 15;
            wv[i] = __ldg((const uint4*)g_W16 + (c * 64 + row) * 16 + seg);
        }
    };
    auto storeXW = [&](int buf) {
        __half* Xp = XsBuf[buf];
        __half* Wp = WsBuf[buf];
#pragma unroll
        for (int i = 0; i < 2; ++i) {
            int idx = tid + i * 256;
            int row = idx >> 3, seg = idx & 7;
            *(uint4*)&Xp[row * XPITCH + seg * 8] = xv[i];
        }
#pragma unroll
        for (int i = 0; i < 4; ++i) {
            int idx = tid + i * 256;
            int row = idx >> 4, seg = idx & 15;
            *(uint4*)&Wp[row * WPITCH + seg * 8] = wv[i];
        }
    };

    loadXW(0);
    storeXW(0);
#pragma unroll 1
    for (int c = 0; c < 6; ++c) {
        __syncthreads();                                 // buf c&1 ready for all
        if (c < 5) loadXW(c + 1);                        // LDG prefetch (regs)
        const __half* Xp = XsBuf[c & 1];
        const __half* Wp = WsBuf[c & 1];
#pragma unroll
        for (int ks = 0; ks < 4; ++ks) {
            uint32_t a[2][4];
            int arow = wm * 32 + (lane & 15);
            int acol = ks * 16 + ((lane >> 4) << 3);
#pragma unroll
            for (int mt = 0; mt < 2; ++mt) {
                uint32_t addr = (uint32_t)__cvta_generic_to_shared(
                    &Xp[(arow + mt * 16) * XPITCH + acol]);
                ldsm_x4(a[mt], addr);
            }
            uint32_t bfr[2][4];
            int krow = ks * 16 + (lane & 7) + (((lane >> 3) & 1) << 3);
            int noff = ((lane >> 4) << 3);
#pragma unroll
            for (int nt4 = 0; nt4 < 2; ++nt4) {
                uint32_t addr = (uint32_t)__cvta_generic_to_shared(
                    &Wp[krow * WPITCH + wn * 32 + nt4 * 16 + noff]);
                ldsm_x4_t(bfr[nt4], addr);
            }
#pragma unroll
            for (int mt = 0; mt < 2; ++mt)
#pragma unroll
                for (int nt = 0; nt < 4; ++nt)
                    mma16816(acc[mt][nt], a[mt],
                             bfr[nt >> 1][(nt & 1) * 2], bfr[nt >> 1][(nt & 1) * 2 + 1]);
        }
        if (c < 5) storeXW((c + 1) & 1);                 // other buffer: no conflict
    }

    // ---- epilogue: + deg*c + b_upd ----
    int colbase = wn * 32 + (lane & 3) * 2;
    float2 cv[4], bv[4];
#pragma unroll
    for (int nt = 0; nt < 4; ++nt) {
        int col = colbase + nt * 8;
        cv[nt] = make_float2(g_c[col], g_c[col + 1]);
        bv[nt] = make_float2(__ldg(&b_upd[col]), __ldg(&b_upd[col + 1]));
    }
#pragma unroll
    for (int mt = 0; mt < 2; ++mt) {
        int row0 = bm + wm * 32 + mt * 16 + (lane >> 2);
        int row1 = row0 + 8;
        float d0 = (row0 < NATOMS) ? (float)g_deg[row0] : 0.f;
        float d1 = (row1 < NATOMS) ? (float)g_deg[row1] : 0.f;
#pragma unroll
        for (int nt = 0; nt < 4; ++nt) {
            int col = colbase + nt * 8;
            if (row0 < NATOMS) {
                float2 o;
                o.x = acc[mt][nt][0] + d0 * cv[nt].x + bv[nt].x;
                o.y = acc[mt][nt][1] + d0 * cv[nt].y + bv[nt].y;
                *(float2*)&out[row0 * F + col] = o;
            }
            if (row1 < NATOMS) {
                float2 o;
                o.x = acc[mt][nt][2] + d1 * cv[nt].x + bv[nt].x;
                o.y = acc[mt][nt][3] + d1 * cv[nt].y + bv[nt].y;
                *(float2*)&out[row1 * F + col] = o;
            }
        }
    }

    // ---- restore invariant: zero this block's g_deg rows for the next call ----
    __syncthreads();                                     // all epilogue reads done
    if (tid < 64) {
        int r = bm + tid;
        if (r < NATOMS) g_deg[r] = 0;
    }
}

// ---------------------------------------------------------------------------
extern "C" void kernel_launch(void* const* d_in, const int* in_sizes, int n_in,
                              void* d_out, int out_size) {
    const float* feat  = (const float*)d_in[0];
    const void*  ei    = d_in[1];
    const float* W_msg = (const float*)d_in[2];
    const float* b_msg = (const float*)d_in[3];
    const float* W_upd = (const float*)d_in[4];
    const float* b_upd = (const float*)d_in[5];
    float*       out   = (float*)d_out;

    static int configured = 0;
    if (!configured) {
        cudaFuncSetAttribute(out_gemm, cudaFuncAttributeMaxDynamicSharedMemorySize,
                             GEMM_SMEM_BYTES);
        configured = 1;
    }

    prebuild_kernel<<<1250, 256>>>(feat, ei, W_msg, b_msg, W_upd);
    gather_kernel<<<(NATOMS * 32 + 255) / 256, 256>>>();
    out_gemm<<<NPAD / 64, 256, GEMM_SMEM_BYTES>>>(b_upd, out);
}